// round 2
// baseline (speedup 1.0000x reference)
#include <cuda_runtime.h>
#include <math.h>

#define Bb   2
#define Ss   2048
#define Hh   1024
#define NHh  16
#define HDd  64
#define RDd  16
#define Ww   16
#define SCALE 0.125f

// ---------------- scratch (device globals: no allocations allowed) ----------
__device__ float g_qkv[(size_t)Bb * Ss * 3 * Hh];   // [B*S, 3H]
__device__ float g_A  [(size_t)Bb * Ss * Hh];       // window-attn out, [B*S, H] == [B,S,NH,HD]
__device__ float g_qa [(size_t)Bb * Ss * Hh];
__device__ float g_ka [(size_t)Bb * Ss * Hh];
__device__ float g_oh [(size_t)Bb * Ss * Hh];       // attention-2 out hidden

// ---------------- generic SGEMM: C[M,N] = X[M,K] @ W[N,K]^T + bias[N] -------
// BM=BN=128, BK=16, 256 threads, 8x8 per thread. M,N,K multiples of 128/16.
__global__ void __launch_bounds__(256) gemm_bias(
    const float* __restrict__ X, const float* __restrict__ W,
    const float* __restrict__ bias, float* __restrict__ C,
    int M, int N, int K)
{
    __shared__ float Xs[16][132];
    __shared__ float Ws[16][132];

    const int bm = blockIdx.y * 128;
    const int bn = blockIdx.x * 128;
    const int tid = threadIdx.x;
    const int tx = tid & 15;
    const int ty = tid >> 4;

    float acc[8][8];
#pragma unroll
    for (int i = 0; i < 8; i++)
#pragma unroll
        for (int j = 0; j < 8; j++) acc[i][j] = 0.f;

    for (int k0 = 0; k0 < K; k0 += 16) {
#pragma unroll
        for (int t = 0; t < 2; t++) {
            int idx = tid + t * 256;            // 0..511
            int r  = idx >> 2;                  // 0..127
            int c4 = (idx & 3) << 2;            // 0,4,8,12
            float4 xv = *(const float4*)(X + (size_t)(bm + r) * K + k0 + c4);
            Xs[c4 + 0][r] = xv.x; Xs[c4 + 1][r] = xv.y;
            Xs[c4 + 2][r] = xv.z; Xs[c4 + 3][r] = xv.w;
            float4 wv = *(const float4*)(W + (size_t)(bn + r) * K + k0 + c4);
            Ws[c4 + 0][r] = wv.x; Ws[c4 + 1][r] = wv.y;
            Ws[c4 + 2][r] = wv.z; Ws[c4 + 3][r] = wv.w;
        }
        __syncthreads();

#pragma unroll
        for (int k = 0; k < 16; k++) {
            float4 a0 = *(const float4*)&Xs[k][ty * 8];
            float4 a1 = *(const float4*)&Xs[k][ty * 8 + 4];
            float4 b0 = *(const float4*)&Ws[k][tx * 8];
            float4 b1 = *(const float4*)&Ws[k][tx * 8 + 4];
            float av[8] = {a0.x, a0.y, a0.z, a0.w, a1.x, a1.y, a1.z, a1.w};
            float bv[8] = {b0.x, b0.y, b0.z, b0.w, b1.x, b1.y, b1.z, b1.w};
#pragma unroll
            for (int i = 0; i < 8; i++)
#pragma unroll
                for (int j = 0; j < 8; j++) acc[i][j] += av[i] * bv[j];
        }
        __syncthreads();
    }

#pragma unroll
    for (int i = 0; i < 8; i++) {
        int row = bm + ty * 8 + i;
        int col = bn + tx * 8;
        float4 o0, o1;
        o0.x = acc[i][0] + bias[col + 0]; o0.y = acc[i][1] + bias[col + 1];
        o0.z = acc[i][2] + bias[col + 2]; o0.w = acc[i][3] + bias[col + 3];
        o1.x = acc[i][4] + bias[col + 4]; o1.y = acc[i][5] + bias[col + 5];
        o1.z = acc[i][6] + bias[col + 6]; o1.w = acc[i][7] + bias[col + 7];
        *(float4*)(C + (size_t)row * N + col)     = o0;
        *(float4*)(C + (size_t)row * N + col + 4) = o1;
    }
}

// ---------------- RoPE on q,k first RD dims (in-place in qkv) ---------------
__global__ void rope_kernel(float* __restrict__ qkv)
{
    int idx = blockIdx.x * blockDim.x + threadIdx.x;
    if (idx >= Bb * Ss * NHh * 2 * (RDd / 2)) return;
    int i  = idx & 7;            // freq index 0..7
    int qk = (idx >> 3) & 1;     // 0=q, 1=k
    int h  = (idx >> 4) & 15;
    int bs = idx >> 8;           // b*S + s
    int s  = bs & (Ss - 1);

    float* p = qkv + (size_t)bs * (3 * Hh) + qk * Hh + h * HDd;
    float inv_freq = powf(10000.f, -(float)(2 * i) / (float)RDd);
    float ang = (float)s * inv_freq;
    float sn, cs;
    sincosf(ang, &sn, &cs);
    float x1 = p[i], x2 = p[i + 8];
    p[i]     = x1 * cs - x2 * sn;
    p[i + 8] = x2 * cs + x1 * sn;
}

// ---------------- sliding-window attention (W=16), warp per query ----------
__global__ void __launch_bounds__(256) window_attn(
    const float* __restrict__ qkv, float* __restrict__ A)
{
    int gw   = (blockIdx.x * blockDim.x + threadIdx.x) >> 5;
    int lane = threadIdx.x & 31;
    // gw over B*NH*S = 65536
    int s = gw & (Ss - 1);
    int h = (gw >> 11) & (NHh - 1);
    int b = gw >> 15;

    const float* qr = qkv + (size_t)(b * Ss + s) * (3 * Hh) + h * HDd;
    float q0 = qr[lane], q1 = qr[lane + 32];

    float sc[Ww];
#pragma unroll
    for (int w = 0; w < Ww; w++) {
        int idx = s - (Ww - 1) + w;
        float p = 0.f;
        if (idx >= 0) {
            const float* kr = qkv + (size_t)(b * Ss + idx) * (3 * Hh) + Hh + h * HDd;
            p = q0 * kr[lane] + q1 * kr[lane + 32];
        }
#pragma unroll
        for (int off = 16; off; off >>= 1)
            p += __shfl_xor_sync(0xffffffffu, p, off);
        sc[w] = (idx >= 0) ? p * SCALE : -1e30f;
    }

    float mx = sc[0];
#pragma unroll
    for (int w = 1; w < Ww; w++) mx = fmaxf(mx, sc[w]);
    float lsum = 0.f;
#pragma unroll
    for (int w = 0; w < Ww; w++) { float e = __expf(sc[w] - mx); sc[w] = e; lsum += e; }
    float inv = 1.f / lsum;

    float o0 = 0.f, o1 = 0.f;
#pragma unroll
    for (int w = 0; w < Ww; w++) {
        int idx = s - (Ww - 1) + w;
        if (idx >= 0) {
            const float* vr = qkv + (size_t)(b * Ss + idx) * (3 * Hh) + 2 * Hh + h * HDd;
            o0 += sc[w] * vr[lane];
            o1 += sc[w] * vr[lane + 32];
        }
    }
    size_t o = (size_t)(b * Ss + s) * Hh + h * HDd;
    A[o + lane]      = o0 * inv;
    A[o + lane + 32] = o1 * inv;
}

// ---------------- full causal attention (flash style, 64x64 tiles) ----------
// out[b,h,q,:] = softmax(causal(qa@ka^T * SCALE)) @ A      -> g_oh [B,S,H]
__global__ void __launch_bounds__(256) flash_attn(
    const float* __restrict__ qa, const float* __restrict__ ka,
    const float* __restrict__ Av, float* __restrict__ Outh)
{
    __shared__ float Qs [64 * 64];   // transposed: Qs[d*64 + r]
    __shared__ float KPs[64 * 64];   // transposed K: KPs[d*64 + c]; reused as P[r*64 + c]
    __shared__ float Vs [64 * 64];   // Vs[c*64 + e]

    const int qt = (int)gridDim.x - 1 - (int)blockIdx.x;   // long blocks first
    const int h  = blockIdx.y;
    const int b  = blockIdx.z;
    const int tid = threadIdx.x;
    const int tx = tid & 15;
    const int ty = tid >> 4;
    const size_t base = (size_t)b * Ss;

    // load Q tile transposed
    for (int i = tid; i < 1024; i += 256) {
        int r = i >> 4, c4 = (i & 15) << 2;
        float4 v = *(const float4*)(qa + (base + qt * 64 + r) * Hh + h * HDd + c4);
        Qs[(c4 + 0) * 64 + r] = v.x; Qs[(c4 + 1) * 64 + r] = v.y;
        Qs[(c4 + 2) * 64 + r] = v.z; Qs[(c4 + 3) * 64 + r] = v.w;
    }

    float m[4], l[4], acc[4][4];
#pragma unroll
    for (int i = 0; i < 4; i++) {
        m[i] = -1e30f; l[i] = 0.f;
#pragma unroll
        for (int j = 0; j < 4; j++) acc[i][j] = 0.f;
    }

    for (int kt = 0; kt <= qt; kt++) {
        __syncthreads();   // previous PV done; Q load done (first iter)
        for (int i = tid; i < 1024; i += 256) {
            int r = i >> 4, c4 = (i & 15) << 2;
            float4 kv = *(const float4*)(ka + (base + kt * 64 + r) * Hh + h * HDd + c4);
            KPs[(c4 + 0) * 64 + r] = kv.x; KPs[(c4 + 1) * 64 + r] = kv.y;
            KPs[(c4 + 2) * 64 + r] = kv.z; KPs[(c4 + 3) * 64 + r] = kv.w;
            float4 vv = *(const float4*)(Av + (base + kt * 64 + r) * Hh + h * HDd + c4);
            *(float4*)&Vs[r * 64 + c4] = vv;
        }
        __syncthreads();

        // S = Q @ K^T
        float sv[4][4];
#pragma unroll
        for (int i = 0; i < 4; i++)
#pragma unroll
            for (int j = 0; j < 4; j++) sv[i][j] = 0.f;

#pragma unroll 16
        for (int d = 0; d < 64; d++) {
            float4 a  = *(const float4*)&Qs [d * 64 + ty * 4];
            float4 bb = *(const float4*)&KPs[d * 64 + tx * 4];
            float av[4] = {a.x, a.y, a.z, a.w};
            float bv[4] = {bb.x, bb.y, bb.z, bb.w};
#pragma unroll
            for (int i = 0; i < 4; i++)
#pragma unroll
                for (int j = 0; j < 4; j++) sv[i][j] += av[i] * bv[j];
        }

#pragma unroll
        for (int i = 0; i < 4; i++)
#pragma unroll
            for (int j = 0; j < 4; j++) sv[i][j] *= SCALE;

        if (kt == qt) {
#pragma unroll
            for (int i = 0; i < 4; i++)
#pragma unroll
                for (int j = 0; j < 4; j++)
                    if (tx * 4 + j > ty * 4 + i) sv[i][j] = -1e30f;
        }

        // online softmax (row groups = 16 threads sharing ty; lanes within 16-group)
        float preg[4][4];
#pragma unroll
        for (int i = 0; i < 4; i++) {
            float rm = fmaxf(fmaxf(sv[i][0], sv[i][1]), fmaxf(sv[i][2], sv[i][3]));
#pragma unroll
            for (int off = 8; off; off >>= 1)
                rm = fmaxf(rm, __shfl_xor_sync(0xffffffffu, rm, off));
            float mnew = fmaxf(m[i], rm);
            float corr = __expf(m[i] - mnew);
            float rs = 0.f;
#pragma unroll
            for (int j = 0; j < 4; j++) {
                float e = __expf(sv[i][j] - mnew);
                preg[i][j] = e; rs += e;
            }
#pragma unroll
            for (int off = 8; off; off >>= 1)
                rs += __shfl_xor_sync(0xffffffffu, rs, off);
            l[i] = l[i] * corr + rs;
#pragma unroll
            for (int j = 0; j < 4; j++) acc[i][j] *= corr;
            m[i] = mnew;
        }

        __syncthreads();   // everyone done reading KPs (K) before overwrite with P
#pragma unroll
        for (int i = 0; i < 4; i++) {
            float4 pv = {preg[i][0], preg[i][1], preg[i][2], preg[i][3]};
            *(float4*)&KPs[(ty * 4 + i) * 64 + tx * 4] = pv;
        }
        __syncthreads();

        // acc += P @ V
#pragma unroll 16
        for (int c = 0; c < 64; c++) {
            float4 vv = *(const float4*)&Vs[c * 64 + tx * 4];
#pragma unroll
            for (int i = 0; i < 4; i++) {
                float p = KPs[(ty * 4 + i) * 64 + c];
                acc[i][0] += p * vv.x; acc[i][1] += p * vv.y;
                acc[i][2] += p * vv.z; acc[i][3] += p * vv.w;
            }
        }
    }

#pragma unroll
    for (int i = 0; i < 4; i++) {
        float invl = 1.f / l[i];
        float4 o = {acc[i][0] * invl, acc[i][1] * invl,
                    acc[i][2] * invl, acc[i][3] * invl};
        *(float4*)(Outh + (base + qt * 64 + ty * 4 + i) * Hh + h * HDd + tx * 4) = o;
    }
}

// ---------------- launch -----------------------------------------------------
extern "C" void kernel_launch(void* const* d_in, const int* in_sizes, int n_in,
                              void* d_out, int out_size)
{
    const float* hs   = (const float*)d_in[0];
    const float* Wqkv = (const float*)d_in[1];
    const float* bqkv = (const float*)d_in[2];
    const float* Wqa  = (const float*)d_in[3];
    const float* bqa  = (const float*)d_in[4];
    const float* Wka  = (const float*)d_in[5];
    const float* bka  = (const float*)d_in[6];
    const float* Wd   = (const float*)d_in[7];
    const float* bd   = (const float*)d_in[8];
    float* out = (float*)d_out;

    float *qkv, *A, *qa, *ka, *oh;
    cudaGetSymbolAddress((void**)&qkv, g_qkv);
    cudaGetSymbolAddress((void**)&A,   g_A);
    cudaGetSymbolAddress((void**)&qa,  g_qa);
    cudaGetSymbolAddress((void**)&ka,  g_ka);
    cudaGetSymbolAddress((void**)&oh,  g_oh);

    const int M = Bb * Ss;          // 4096

    // 1) qkv = hs @ Wqkv^T + bqkv
    gemm_bias<<<dim3(3 * Hh / 128, M / 128), 256>>>(hs, Wqkv, bqkv, qkv, M, 3 * Hh, Hh);

    // 2) RoPE in-place on q,k
    {
        int total = Bb * Ss * NHh * 2 * (RDd / 2);
        rope_kernel<<<(total + 255) / 256, 256>>>(qkv);
    }

    // 3) sliding-window attention -> A
    window_attn<<<(Bb * NHh * Ss) * 32 / 256, 256>>>(qkv, A);

    // 4) qa = A @ Wqa^T + bqa ; ka = A @ Wka^T + bka
    gemm_bias<<<dim3(Hh / 128, M / 128), 256>>>(A, Wqa, bqa, qa, M, Hh, Hh);
    gemm_bias<<<dim3(Hh / 128, M / 128), 256>>>(A, Wka, bka, ka, M, Hh, Hh);

    // 5) full causal attention -> oh
    flash_attn<<<dim3(Ss / 64, NHh, Bb), 256>>>(qa, ka, A, oh);

    // 6) out = oh @ Wd^T + bd
    gemm_bias<<<dim3(Hh / 128, M / 128), 256>>>(oh, Wd, bd, out, M, Hh, Hh);
}

// round 6
// speedup vs baseline: 1.5346x; 1.5346x over previous
#include <cuda_runtime.h>
#include <cuda_bf16.h>
#include <math.h>
#include <stdint.h>

#define Bb   2
#define Ss   2048
#define Hh   1024
#define NHh  16
#define HDd  64
#define RDd  16
#define Ww   16
#define SCALE 0.125f

// split width: [hi | lo-or-hi | hi-or-lo] along K
#define KP   3072
#define NIT  (KP / 32)

// ---------------- scratch (device globals: no allocations allowed) ----------
__device__ float g_qkv[(size_t)Bb * Ss * 3 * Hh];   // [B*S, 3H]
__device__ float g_A  [(size_t)Bb * Ss * Hh];       // window-attn out
__device__ float g_qa [(size_t)Bb * Ss * Hh];
__device__ float g_ka [(size_t)Bb * Ss * Hh];
__device__ float g_oh [(size_t)Bb * Ss * Hh];

// bf16 3-segment split operands, layout [rows, 3072]
__device__ __nv_bfloat16 g_hs2  [(size_t)Bb * Ss * KP];
__device__ __nv_bfloat16 g_A2   [(size_t)Bb * Ss * KP];
__device__ __nv_bfloat16 g_oh2  [(size_t)Bb * Ss * KP];
__device__ __nv_bfloat16 g_Wqkv2[(size_t)3 * Hh * KP];
__device__ __nv_bfloat16 g_Wqa2 [(size_t)Hh * KP];
__device__ __nv_bfloat16 g_Wka2 [(size_t)Hh * KP];
__device__ __nv_bfloat16 g_Wd2  [(size_t)Hh * KP];

// =================== helpers ================================================
__device__ __forceinline__ uint32_t smem_u32(const void* p) {
    uint32_t a;
    asm("{ .reg .u64 t; cvta.to.shared.u64 t, %1; cvt.u32.u64 %0, t; }" : "=r"(a) : "l"(p));
    return a;
}
__device__ __forceinline__ void cp_async16(void* s, const void* g) {
    uint32_t sa = smem_u32(s);
    asm volatile("cp.async.ca.shared.global [%0], [%1], 16;" :: "r"(sa), "l"(g));
}
#define CP_COMMIT() asm volatile("cp.async.commit_group;" ::: "memory")
#define CP_WAIT1()  asm volatile("cp.async.wait_group 1;" ::: "memory")
#define CP_WAIT0()  asm volatile("cp.async.wait_group 0;" ::: "memory")

__device__ __forceinline__ void ldmat_x4(uint32_t* r, uint32_t addr) {
    asm volatile("ldmatrix.sync.aligned.m8n8.x4.shared.b16 {%0,%1,%2,%3}, [%4];"
        : "=r"(r[0]), "=r"(r[1]), "=r"(r[2]), "=r"(r[3]) : "r"(addr));
}
__device__ __forceinline__ void mma_bf16(float* d, const uint32_t* a, const uint32_t* b) {
    asm volatile(
        "mma.sync.aligned.m16n8k16.row.col.f32.bf16.bf16.f32 "
        "{%0,%1,%2,%3}, {%4,%5,%6,%7}, {%8,%9}, {%0,%1,%2,%3};"
        : "+f"(d[0]), "+f"(d[1]), "+f"(d[2]), "+f"(d[3])
        : "r"(a[0]), "r"(a[1]), "r"(a[2]), "r"(a[3]), "r"(b[0]), "r"(b[1]));
}

// ====== fp32 -> bf16 3-segment split ========================================
// mode 0 (A-side): [hi | lo | hi] ; mode 1 (B-side): [hi | hi | lo]
__global__ void split_bf16(const float* __restrict__ X, __nv_bfloat16* __restrict__ Y,
                           int n4, int mode)
{
    int i = blockIdx.x * blockDim.x + threadIdx.x;
    if (i >= n4) return;
    int base = i << 2;
    float4 v = *(const float4*)(X + base);
    int r = base >> 10;          // K=1024 source row
    int c = base & 1023;
    __nv_bfloat16 h0 = __float2bfloat16(v.x), h1 = __float2bfloat16(v.y);
    __nv_bfloat16 h2 = __float2bfloat16(v.z), h3 = __float2bfloat16(v.w);
    __nv_bfloat16 l0 = __float2bfloat16(v.x - __bfloat162float(h0));
    __nv_bfloat16 l1 = __float2bfloat16(v.y - __bfloat162float(h1));
    __nv_bfloat16 l2 = __float2bfloat16(v.z - __bfloat162float(h2));
    __nv_bfloat16 l3 = __float2bfloat16(v.w - __bfloat162float(h3));
    __nv_bfloat16* row = Y + (size_t)r * KP + c;
    __nv_bfloat162 hA = __nv_bfloat162(h0, h1), hB = __nv_bfloat162(h2, h3);
    __nv_bfloat162 lA = __nv_bfloat162(l0, l1), lB = __nv_bfloat162(l2, l3);
    // seg0: hi
    ((__nv_bfloat162*)(row))[0] = hA; ((__nv_bfloat162*)(row))[1] = hB;
    if (mode == 0) {   // A-side: [hi | lo | hi]
        ((__nv_bfloat162*)(row + 1024))[0] = lA; ((__nv_bfloat162*)(row + 1024))[1] = lB;
        ((__nv_bfloat162*)(row + 2048))[0] = hA; ((__nv_bfloat162*)(row + 2048))[1] = hB;
    } else {           // B-side: [hi | hi | lo]
        ((__nv_bfloat162*)(row + 1024))[0] = hA; ((__nv_bfloat162*)(row + 1024))[1] = hB;
        ((__nv_bfloat162*)(row + 2048))[0] = lA; ((__nv_bfloat162*)(row + 2048))[1] = lB;
    }
}

// ======== HMMA GEMM:  C[M,N] = A2[M,3072] @ B2[N,3072]^T + bias[N] ==========
// BM=BN=128, BK=32 bf16, 8 warps (2x4), warp tile 64x32, double-buffered cp.async.
__global__ void __launch_bounds__(256) hmma_gemm(
    const __nv_bfloat16* __restrict__ A2, const __nv_bfloat16* __restrict__ B2,
    const float* __restrict__ bias, float* __restrict__ C, int M, int N)
{
    // [buf][A=0/B=1][row 0..127][col 0..39]  (pad 32->40: 80B row, conflict-free)
    __shared__ __align__(16) __nv_bfloat16 sm[2][2][128][40];

    const int tid = threadIdx.x;
    const int wid = tid >> 5;
    const int lane = tid & 31;
    const int bm = blockIdx.y * 128;
    const int bn = blockIdx.x * 128;
    const int wm = wid & 1;          // warp row (0..1) -> 64 rows
    const int wn = wid >> 1;         // warp col (0..3) -> 32 cols

    float acc[4][4][4];
#pragma unroll
    for (int mi = 0; mi < 4; mi++)
#pragma unroll
        for (int ni = 0; ni < 4; ni++)
#pragma unroll
            for (int q = 0; q < 4; q++) acc[mi][ni][q] = 0.f;

    auto load_tile = [&](int buf, int k0) {
#pragma unroll
        for (int i = 0; i < 2; i++) {
            int c = tid + i * 256;      // 0..511
            int r = c >> 2;             // 0..127
            int kk = (c & 3) * 8;       // 0,8,16,24 elems (16B chunks)
            cp_async16(&sm[buf][0][r][kk], A2 + (size_t)(bm + r) * KP + k0 + kk);
            cp_async16(&sm[buf][1][r][kk], B2 + (size_t)(bn + r) * KP + k0 + kk);
        }
        CP_COMMIT();
    };

    load_tile(0, 0);

    for (int it = 0; it < NIT; it++) {
        const int buf = it & 1;
        if (it + 1 < NIT) {
            load_tile(buf ^ 1, (it + 1) * 32);
            CP_WAIT1();
        } else {
            CP_WAIT0();
        }
        __syncthreads();

#pragma unroll
        for (int ks = 0; ks < 2; ks++) {
            uint32_t af[4][4];
#pragma unroll
            for (int mi = 0; mi < 4; mi++) {
                uint32_t addr = smem_u32(
                    &sm[buf][0][wm * 64 + mi * 16 + (lane & 15)][ks * 16 + (lane >> 4) * 8]);
                ldmat_x4(af[mi], addr);
            }
            uint32_t bf[2][4];
#pragma unroll
            for (int g = 0; g < 2; g++) {
                uint32_t addr = smem_u32(
                    &sm[buf][1][wn * 32 + g * 16 + (lane & 7) + ((lane >> 4) & 1) * 8]
                               [ks * 16 + ((lane >> 3) & 1) * 8]);
                ldmat_x4(bf[g], addr);
            }
#pragma unroll
            for (int mi = 0; mi < 4; mi++)
#pragma unroll
                for (int ni = 0; ni < 4; ni++) {
                    uint32_t bb[2] = {bf[ni >> 1][(ni & 1) * 2],
                                      bf[ni >> 1][(ni & 1) * 2 + 1]};
                    mma_bf16(acc[mi][ni], af[mi], bb);
                }
        }
        __syncthreads();
    }

    // epilogue: fragment-direct stores + bias
#pragma unroll
    for (int mi = 0; mi < 4; mi++) {
        int row0 = bm + wm * 64 + mi * 16 + (lane >> 2);
#pragma unroll
        for (int ni = 0; ni < 4; ni++) {
            int col = bn + wn * 32 + ni * 8 + (lane & 3) * 2;
            float b0 = bias[col], b1 = bias[col + 1];
            float2 v0 = {acc[mi][ni][0] + b0, acc[mi][ni][1] + b1};
            float2 v1 = {acc[mi][ni][2] + b0, acc[mi][ni][3] + b1};
            *(float2*)(C + (size_t)row0 * N + col)       = v0;
            *(float2*)(C + (size_t)(row0 + 8) * N + col) = v1;
        }
    }
}

// ---------------- RoPE on q,k first RD dims (in-place in qkv) ---------------
__global__ void rope_kernel(float* __restrict__ qkv)
{
    int idx = blockIdx.x * blockDim.x + threadIdx.x;
    if (idx >= Bb * Ss * NHh * 2 * (RDd / 2)) return;
    int i  = idx & 7;
    int qk = (idx >> 3) & 1;
    int h  = (idx >> 4) & 15;
    int bs = idx >> 8;
    int s  = bs & (Ss - 1);

    float* p = qkv + (size_t)bs * (3 * Hh) + qk * Hh + h * HDd;
    float inv_freq = powf(10000.f, -(float)(2 * i) / (float)RDd);
    float ang = (float)s * inv_freq;
    float sn, cs;
    sincosf(ang, &sn, &cs);
    float x1 = p[i], x2 = p[i + 8];
    p[i]     = x1 * cs - x2 * sn;
    p[i + 8] = x2 * cs + x1 * sn;
}

// ---------------- sliding-window attention (W=16), warp per query ----------
__global__ void __launch_bounds__(256) window_attn(
    const float* __restrict__ qkv, float* __restrict__ A)
{
    int gw   = (blockIdx.x * blockDim.x + threadIdx.x) >> 5;
    int lane = threadIdx.x & 31;
    int s = gw & (Ss - 1);
    int h = (gw >> 11) & (NHh - 1);
    int b = gw >> 15;

    const float* qr = qkv + (size_t)(b * Ss + s) * (3 * Hh) + h * HDd;
    float q0 = qr[lane], q1 = qr[lane + 32];

    float sc[Ww];
#pragma unroll
    for (int w = 0; w < Ww; w++) {
        int idx = s - (Ww - 1) + w;
        float p = 0.f;
        if (idx >= 0) {
            const float* kr = qkv + (size_t)(b * Ss + idx) * (3 * Hh) + Hh + h * HDd;
            p = q0 * kr[lane] + q1 * kr[lane + 32];
        }
#pragma unroll
        for (int off = 16; off; off >>= 1)
            p += __shfl_xor_sync(0xffffffffu, p, off);
        sc[w] = (idx >= 0) ? p * SCALE : -1e30f;
    }

    float mx = sc[0];
#pragma unroll
    for (int w = 1; w < Ww; w++) mx = fmaxf(mx, sc[w]);
    float lsum = 0.f;
#pragma unroll
    for (int w = 0; w < Ww; w++) { float e = __expf(sc[w] - mx); sc[w] = e; lsum += e; }
    float inv = 1.f / lsum;

    float o0 = 0.f, o1 = 0.f;
#pragma unroll
    for (int w = 0; w < Ww; w++) {
        int idx = s - (Ww - 1) + w;
        if (idx >= 0) {
            const float* vr = qkv + (size_t)(b * Ss + idx) * (3 * Hh) + 2 * Hh + h * HDd;
            o0 += sc[w] * vr[lane];
            o1 += sc[w] * vr[lane + 32];
        }
    }
    size_t o = (size_t)(b * Ss + s) * Hh + h * HDd;
    A[o + lane]      = o0 * inv;
    A[o + lane + 32] = o1 * inv;
}

// ---------------- full causal attention (flash style, 64x64 tiles) ----------
__global__ void __launch_bounds__(256) flash_attn(
    const float* __restrict__ qa, const float* __restrict__ ka,
    const float* __restrict__ Av, float* __restrict__ Outh)
{
    __shared__ float Qs [64 * 64];
    __shared__ float KPs[64 * 64];
    __shared__ float Vs [64 * 64];

    const int qt = (int)gridDim.x - 1 - (int)blockIdx.x;
    const int h  = blockIdx.y;
    const int b  = blockIdx.z;
    const int tid = threadIdx.x;
    const int tx = tid & 15;
    const int ty = tid >> 4;
    const size_t base = (size_t)b * Ss;

    for (int i = tid; i < 1024; i += 256) {
        int r = i >> 4, c4 = (i & 15) << 2;
        float4 v = *(const float4*)(qa + (base + qt * 64 + r) * Hh + h * HDd + c4);
        Qs[(c4 + 0) * 64 + r] = v.x; Qs[(c4 + 1) * 64 + r] = v.y;
        Qs[(c4 + 2) * 64 + r] = v.z; Qs[(c4 + 3) * 64 + r] = v.w;
    }

    float m[4], l[4], acc[4][4];
#pragma unroll
    for (int i = 0; i < 4; i++) {
        m[i] = -1e30f; l[i] = 0.f;
#pragma unroll
        for (int j = 0; j < 4; j++) acc[i][j] = 0.f;
    }

    for (int kt = 0; kt <= qt; kt++) {
        __syncthreads();
        for (int i = tid; i < 1024; i += 256) {
            int r = i >> 4, c4 = (i & 15) << 2;
            float4 kv = *(const float4*)(ka + (base + kt * 64 + r) * Hh + h * HDd + c4);
            KPs[(c4 + 0) * 64 + r] = kv.x; KPs[(c4 + 1) * 64 + r] = kv.y;
            KPs[(c4 + 2) * 64 + r] = kv.z; KPs[(c4 + 3) * 64 + r] = kv.w;
            float4 vv = *(const float4*)(Av + (base + kt * 64 + r) * Hh + h * HDd + c4);
            *(float4*)&Vs[r * 64 + c4] = vv;
        }
        __syncthreads();

        float sv[4][4];
#pragma unroll
        for (int i = 0; i < 4; i++)
#pragma unroll
            for (int j = 0; j < 4; j++) sv[i][j] = 0.f;

#pragma unroll 16
        for (int d = 0; d < 64; d++) {
            float4 a  = *(const float4*)&Qs [d * 64 + ty * 4];
            float4 bb = *(const float4*)&KPs[d * 64 + tx * 4];
            float av[4] = {a.x, a.y, a.z, a.w};
            float bv[4] = {bb.x, bb.y, bb.z, bb.w};
#pragma unroll
            for (int i = 0; i < 4; i++)
#pragma unroll
                for (int j = 0; j < 4; j++) sv[i][j] += av[i] * bv[j];
        }

#pragma unroll
        for (int i = 0; i < 4; i++)
#pragma unroll
            for (int j = 0; j < 4; j++) sv[i][j] *= SCALE;

        if (kt == qt) {
#pragma unroll
            for (int i = 0; i < 4; i++)
#pragma unroll
                for (int j = 0; j < 4; j++)
                    if (tx * 4 + j > ty * 4 + i) sv[i][j] = -1e30f;
        }

        float preg[4][4];
#pragma unroll
        for (int i = 0; i < 4; i++) {
            float rm = fmaxf(fmaxf(sv[i][0], sv[i][1]), fmaxf(sv[i][2], sv[i][3]));
#pragma unroll
            for (int off = 8; off; off >>= 1)
                rm = fmaxf(rm, __shfl_xor_sync(0xffffffffu, rm, off));
            float mnew = fmaxf(m[i], rm);
            float corr = __expf(m[i] - mnew);
            float rs = 0.f;
#pragma unroll
            for (int j = 0; j < 4; j++) {
                float e = __expf(sv[i][j] - mnew);
                preg[i][j] = e; rs += e;
            }
#pragma unroll
            for (int off = 8; off; off >>= 1)
                rs += __shfl_xor_sync(0xffffffffu, rs, off);
            l[i] = l[i] * corr + rs;
#pragma unroll
            for (int j = 0; j < 4; j++) acc[i][j] *= corr;
            m[i] = mnew;
        }

        __syncthreads();
#pragma unroll
        for (int i = 0; i < 4; i++) {
            float4 pv = {preg[i][0], preg[i][1], preg[i][2], preg[i][3]};
            *(float4*)&KPs[(ty * 4 + i) * 64 + tx * 4] = pv;
        }
        __syncthreads();

#pragma unroll 16
        for (int c = 0; c < 64; c++) {
            float4 vv = *(const float4*)&Vs[c * 64 + tx * 4];
#pragma unroll
            for (int i = 0; i < 4; i++) {
                float p = KPs[(ty * 4 + i) * 64 + c];
                acc[i][0] += p * vv.x; acc[i][1] += p * vv.y;
                acc[i][2] += p * vv.z; acc[i][3] += p * vv.w;
            }
        }
    }

#pragma unroll
    for (int i = 0; i < 4; i++) {
        float invl = 1.f / l[i];
        float4 o = {acc[i][0] * invl, acc[i][1] * invl,
                    acc[i][2] * invl, acc[i][3] * invl};
        *(float4*)(Outh + (base + qt * 64 + ty * 4 + i) * Hh + h * HDd + tx * 4) = o;
    }
}

// ---------------- launch -----------------------------------------------------
extern "C" void kernel_launch(void* const* d_in, const int* in_sizes, int n_in,
                              void* d_out, int out_size)
{
    const float* hs   = (const float*)d_in[0];
    const float* Wqkv = (const float*)d_in[1];
    const float* bqkv = (const float*)d_in[2];
    const float* Wqa  = (const float*)d_in[3];
    const float* bqa  = (const float*)d_in[4];
    const float* Wka  = (const float*)d_in[5];
    const float* bka  = (const float*)d_in[6];
    const float* Wd   = (const float*)d_in[7];
    const float* bd   = (const float*)d_in[8];
    float* out = (float*)d_out;

    float *qkv, *A, *qa, *ka, *oh;
    __nv_bfloat16 *hs2, *A2, *oh2, *Wqkv2, *Wqa2, *Wka2, *Wd2;
    cudaGetSymbolAddress((void**)&qkv, g_qkv);
    cudaGetSymbolAddress((void**)&A,   g_A);
    cudaGetSymbolAddress((void**)&qa,  g_qa);
    cudaGetSymbolAddress((void**)&ka,  g_ka);
    cudaGetSymbolAddress((void**)&oh,  g_oh);
    cudaGetSymbolAddress((void**)&hs2,   g_hs2);
    cudaGetSymbolAddress((void**)&A2,    g_A2);
    cudaGetSymbolAddress((void**)&oh2,   g_oh2);
    cudaGetSymbolAddress((void**)&Wqkv2, g_Wqkv2);
    cudaGetSymbolAddress((void**)&Wqa2,  g_Wqa2);
    cudaGetSymbolAddress((void**)&Wka2,  g_Wka2);
    cudaGetSymbolAddress((void**)&Wd2,   g_Wd2);

    const int M = Bb * Ss;          // 4096

    auto conv = [](const float* x, __nv_bfloat16* y, int elems, int mode) {
        int n4 = elems / 4;
        split_bf16<<<(n4 + 255) / 256, 256>>>(x, y, n4, mode);
    };

    conv(hs,   hs2,   M * Hh,      0);   // A-side
    conv(Wqkv, Wqkv2, 3 * Hh * Hh, 1);   // B-side
    conv(Wqa,  Wqa2,  Hh * Hh,     1);
    conv(Wka,  Wka2,  Hh * Hh,     1);
    conv(Wd,   Wd2,   Hh * Hh,     1);

    // 1) qkv = hs @ Wqkv^T + bqkv
    hmma_gemm<<<dim3(3 * Hh / 128, M / 128), 256>>>(hs2, Wqkv2, bqkv, qkv, M, 3 * Hh);

    // 2) RoPE in-place on q,k
    {
        int total = Bb * Ss * NHh * 2 * (RDd / 2);
        rope_kernel<<<(total + 255) / 256, 256>>>(qkv);
    }

    // 3) sliding-window attention -> A
    window_attn<<<(Bb * NHh * Ss) * 32 / 256, 256>>>(qkv, A);

    // 4) qa = A @ Wqa^T + bqa ; ka = A @ Wka^T + bka
    conv(A, A2, M * Hh, 0);
    hmma_gemm<<<dim3(Hh / 128, M / 128), 256>>>(A2, Wqa2, bqa, qa, M, Hh);
    hmma_gemm<<<dim3(Hh / 128, M / 128), 256>>>(A2, Wka2, bka, ka, M, Hh);

    // 5) full causal attention -> oh
    flash_attn<<<dim3(Ss / 64, NHh, Bb), 256>>>(qa, ka, A, oh);

    // 6) out = oh @ Wd^T + bd
    conv(oh, oh2, M * Hh, 0);
    hmma_gemm<<<dim3(Hh / 128, M / 128), 256>>>(oh2, Wd2, bd, out, M, Hh);
}

// round 7
// speedup vs baseline: 2.2944x; 1.4951x over previous
#include <cuda_runtime.h>
#include <cuda_bf16.h>
#include <math.h>
#include <stdint.h>

#define Bb   2
#define Ss   2048
#define Hh   1024
#define NHh  16
#define HDd  64
#define RDd  16
#define Ww   16
#define SCALE 0.125f

// GEMM split width: [hi | lo | hi] x [hi | hi | lo] along K
#define KP   3072
#define NIT  (KP / 32)

// ---------------- scratch (device globals: no allocations allowed) ----------
__device__ float g_qkv[(size_t)Bb * Ss * 3 * Hh];   // [B*S, 3H]
__device__ float g_A  [(size_t)Bb * Ss * Hh];       // window-attn out
__device__ float g_qa [(size_t)Bb * Ss * Hh];
__device__ float g_ka [(size_t)Bb * Ss * Hh];
__device__ float g_oh [(size_t)Bb * Ss * Hh];

// bf16 3-segment split operands, layout [rows, 3072]
__device__ __nv_bfloat16 g_hs2  [(size_t)Bb * Ss * KP];
__device__ __nv_bfloat16 g_A2   [(size_t)Bb * Ss * KP];
__device__ __nv_bfloat16 g_oh2  [(size_t)Bb * Ss * KP];
__device__ __nv_bfloat16 g_Wqkv2[(size_t)3 * Hh * KP];
__device__ __nv_bfloat16 g_Wqa2 [(size_t)Hh * KP];
__device__ __nv_bfloat16 g_Wka2 [(size_t)Hh * KP];
__device__ __nv_bfloat16 g_Wd2  [(size_t)Hh * KP];

// flash attention operands
__device__ __nv_bfloat16 g_Q2 [(size_t)Bb * NHh * Ss * 192];  // [bh, s, 192] hi|lo|hi
__device__ __nv_bfloat16 g_K2 [(size_t)Bb * NHh * Ss * 192];  // [bh, s, 192] hi|hi|lo
__device__ __nv_bfloat16 g_Vth[(size_t)Bb * NHh * HDd * Ss];  // [bh*64+d, s] hi
__device__ __nv_bfloat16 g_Vtl[(size_t)Bb * NHh * HDd * Ss];  // [bh*64+d, s] lo

// =================== helpers ================================================
__device__ __forceinline__ uint32_t smem_u32(const void* p) {
    uint32_t a;
    asm("{ .reg .u64 t; cvta.to.shared.u64 t, %1; cvt.u32.u64 %0, t; }" : "=r"(a) : "l"(p));
    return a;
}
__device__ __forceinline__ void cp_async16(void* s, const void* g) {
    uint32_t sa = smem_u32(s);
    asm volatile("cp.async.ca.shared.global [%0], [%1], 16;" :: "r"(sa), "l"(g));
}
#define CP_COMMIT() asm volatile("cp.async.commit_group;" ::: "memory")
#define CP_WAIT1()  asm volatile("cp.async.wait_group 1;" ::: "memory")
#define CP_WAIT0()  asm volatile("cp.async.wait_group 0;" ::: "memory")

__device__ __forceinline__ void ldmat_x4(uint32_t* r, uint32_t addr) {
    asm volatile("ldmatrix.sync.aligned.m8n8.x4.shared.b16 {%0,%1,%2,%3}, [%4];"
        : "=r"(r[0]), "=r"(r[1]), "=r"(r[2]), "=r"(r[3]) : "r"(addr));
}
__device__ __forceinline__ void mma_bf16(float* d, const uint32_t* a, const uint32_t* b) {
    asm volatile(
        "mma.sync.aligned.m16n8k16.row.col.f32.bf16.bf16.f32 "
        "{%0,%1,%2,%3}, {%4,%5,%6,%7}, {%8,%9}, {%0,%1,%2,%3};"
        : "+f"(d[0]), "+f"(d[1]), "+f"(d[2]), "+f"(d[3])
        : "r"(a[0]), "r"(a[1]), "r"(a[2]), "r"(a[3]), "r"(b[0]), "r"(b[1]));
}
__device__ __forceinline__ uint32_t pack_bf2(float x, float y) {
    __nv_bfloat162 t(__float2bfloat16(x), __float2bfloat16(y));
    return *(uint32_t*)&t;
}

// ====== fp32 -> bf16 3-segment split (GEMM operands) ========================
__global__ void split_bf16(const float* __restrict__ X, __nv_bfloat16* __restrict__ Y,
                           int n4, int mode)
{
    int i = blockIdx.x * blockDim.x + threadIdx.x;
    if (i >= n4) return;
    int base = i << 2;
    float4 v = *(const float4*)(X + base);
    int r = base >> 10;
    int c = base & 1023;
    __nv_bfloat16 h0 = __float2bfloat16(v.x), h1 = __float2bfloat16(v.y);
    __nv_bfloat16 h2 = __float2bfloat16(v.z), h3 = __float2bfloat16(v.w);
    __nv_bfloat16 l0 = __float2bfloat16(v.x - __bfloat162float(h0));
    __nv_bfloat16 l1 = __float2bfloat16(v.y - __bfloat162float(h1));
    __nv_bfloat16 l2 = __float2bfloat16(v.z - __bfloat162float(h2));
    __nv_bfloat16 l3 = __float2bfloat16(v.w - __bfloat162float(h3));
    __nv_bfloat16* row = Y + (size_t)r * KP + c;
    __nv_bfloat162 hA(h0, h1), hB(h2, h3), lA(l0, l1), lB(l2, l3);
    ((__nv_bfloat162*)(row))[0] = hA; ((__nv_bfloat162*)(row))[1] = hB;
    if (mode == 0) {   // A-side: [hi | lo | hi]
        ((__nv_bfloat162*)(row + 1024))[0] = lA; ((__nv_bfloat162*)(row + 1024))[1] = lB;
        ((__nv_bfloat162*)(row + 2048))[0] = hA; ((__nv_bfloat162*)(row + 2048))[1] = hB;
    } else {           // B-side: [hi | hi | lo]
        ((__nv_bfloat162*)(row + 1024))[0] = hA; ((__nv_bfloat162*)(row + 1024))[1] = hB;
        ((__nv_bfloat162*)(row + 2048))[0] = lA; ((__nv_bfloat162*)(row + 2048))[1] = lB;
    }
}

// ======== HMMA GEMM:  C[M,N] = A2[M,3072] @ B2[N,3072]^T + bias[N] ==========
__global__ void __launch_bounds__(256) hmma_gemm(
    const __nv_bfloat16* __restrict__ A2, const __nv_bfloat16* __restrict__ B2,
    const float* __restrict__ bias, float* __restrict__ C, int M, int N)
{
    __shared__ __align__(16) __nv_bfloat16 sm[2][2][128][40];

    const int tid = threadIdx.x;
    const int wid = tid >> 5;
    const int lane = tid & 31;
    const int bm = blockIdx.y * 128;
    const int bn = blockIdx.x * 128;
    const int wm = wid & 1;
    const int wn = wid >> 1;

    float acc[4][4][4];
#pragma unroll
    for (int mi = 0; mi < 4; mi++)
#pragma unroll
        for (int ni = 0; ni < 4; ni++)
#pragma unroll
            for (int q = 0; q < 4; q++) acc[mi][ni][q] = 0.f;

    auto load_tile = [&](int buf, int k0) {
#pragma unroll
        for (int i = 0; i < 2; i++) {
            int c = tid + i * 256;
            int r = c >> 2;
            int kk = (c & 3) * 8;
            cp_async16(&sm[buf][0][r][kk], A2 + (size_t)(bm + r) * KP + k0 + kk);
            cp_async16(&sm[buf][1][r][kk], B2 + (size_t)(bn + r) * KP + k0 + kk);
        }
        CP_COMMIT();
    };

    load_tile(0, 0);

    for (int it = 0; it < NIT; it++) {
        const int buf = it & 1;
        if (it + 1 < NIT) {
            load_tile(buf ^ 1, (it + 1) * 32);
            CP_WAIT1();
        } else {
            CP_WAIT0();
        }
        __syncthreads();

#pragma unroll
        for (int ks = 0; ks < 2; ks++) {
            uint32_t af[4][4];
#pragma unroll
            for (int mi = 0; mi < 4; mi++) {
                uint32_t addr = smem_u32(
                    &sm[buf][0][wm * 64 + mi * 16 + (lane & 15)][ks * 16 + (lane >> 4) * 8]);
                ldmat_x4(af[mi], addr);
            }
            uint32_t bf[2][4];
#pragma unroll
            for (int g = 0; g < 2; g++) {
                uint32_t addr = smem_u32(
                    &sm[buf][1][wn * 32 + g * 16 + (lane & 7) + ((lane >> 4) & 1) * 8]
                               [ks * 16 + ((lane >> 3) & 1) * 8]);
                ldmat_x4(bf[g], addr);
            }
#pragma unroll
            for (int mi = 0; mi < 4; mi++)
#pragma unroll
                for (int ni = 0; ni < 4; ni++) {
                    uint32_t bb[2] = {bf[ni >> 1][(ni & 1) * 2],
                                      bf[ni >> 1][(ni & 1) * 2 + 1]};
                    mma_bf16(acc[mi][ni], af[mi], bb);
                }
        }
        __syncthreads();
    }

#pragma unroll
    for (int mi = 0; mi < 4; mi++) {
        int row0 = bm + wm * 64 + mi * 16 + (lane >> 2);
#pragma unroll
        for (int ni = 0; ni < 4; ni++) {
            int col = bn + wn * 32 + ni * 8 + (lane & 3) * 2;
            float b0 = bias[col], b1 = bias[col + 1];
            float2 v0 = {acc[mi][ni][0] + b0, acc[mi][ni][1] + b1};
            float2 v1 = {acc[mi][ni][2] + b0, acc[mi][ni][3] + b1};
            *(float2*)(C + (size_t)row0 * N + col)       = v0;
            *(float2*)(C + (size_t)(row0 + 8) * N + col) = v1;
        }
    }
}

// ---------------- RoPE on q,k first RD dims (in-place in qkv) ---------------
__global__ void rope_kernel(float* __restrict__ qkv)
{
    int idx = blockIdx.x * blockDim.x + threadIdx.x;
    if (idx >= Bb * Ss * NHh * 2 * (RDd / 2)) return;
    int i  = idx & 7;
    int qk = (idx >> 3) & 1;
    int h  = (idx >> 4) & 15;
    int bs = idx >> 8;
    int s  = bs & (Ss - 1);

    float* p = qkv + (size_t)bs * (3 * Hh) + qk * Hh + h * HDd;
    float inv_freq = powf(10000.f, -(float)(2 * i) / (float)RDd);
    float ang = (float)s * inv_freq;
    float sn, cs;
    sincosf(ang, &sn, &cs);
    float x1 = p[i], x2 = p[i + 8];
    p[i]     = x1 * cs - x2 * sn;
    p[i + 8] = x2 * cs + x1 * sn;
}

// ---------------- sliding-window attention (W=16), warp per query ----------
__global__ void __launch_bounds__(256) window_attn(
    const float* __restrict__ qkv, float* __restrict__ A)
{
    int gw   = (blockIdx.x * blockDim.x + threadIdx.x) >> 5;
    int lane = threadIdx.x & 31;
    int s = gw & (Ss - 1);
    int h = (gw >> 11) & (NHh - 1);
    int b = gw >> 15;

    const float* qr = qkv + (size_t)(b * Ss + s) * (3 * Hh) + h * HDd;
    float q0 = qr[lane], q1 = qr[lane + 32];

    float sc[Ww];
#pragma unroll
    for (int w = 0; w < Ww; w++) {
        int idx = s - (Ww - 1) + w;
        float p = 0.f;
        if (idx >= 0) {
            const float* kr = qkv + (size_t)(b * Ss + idx) * (3 * Hh) + Hh + h * HDd;
            p = q0 * kr[lane] + q1 * kr[lane + 32];
        }
#pragma unroll
        for (int off = 16; off; off >>= 1)
            p += __shfl_xor_sync(0xffffffffu, p, off);
        sc[w] = (idx >= 0) ? p * SCALE : -1e30f;
    }

    float mx = sc[0];
#pragma unroll
    for (int w = 1; w < Ww; w++) mx = fmaxf(mx, sc[w]);
    float lsum = 0.f;
#pragma unroll
    for (int w = 0; w < Ww; w++) { float e = __expf(sc[w] - mx); sc[w] = e; lsum += e; }
    float inv = 1.f / lsum;

    float o0 = 0.f, o1 = 0.f;
#pragma unroll
    for (int w = 0; w < Ww; w++) {
        int idx = s - (Ww - 1) + w;
        if (idx >= 0) {
            const float* vr = qkv + (size_t)(b * Ss + idx) * (3 * Hh) + 2 * Hh + h * HDd;
            o0 += sc[w] * vr[lane];
            o1 += sc[w] * vr[lane + 32];
        }
    }
    size_t o = (size_t)(b * Ss + s) * Hh + h * HDd;
    A[o + lane]      = o0 * inv;
    A[o + lane + 32] = o1 * inv;
}

// ====== qa/ka -> per-head split layout [bh, s, 192] =========================
__global__ void qk_split(const float* __restrict__ qa, const float* __restrict__ ka,
                         __nv_bfloat16* __restrict__ Q2, __nv_bfloat16* __restrict__ K2)
{
    int i = blockIdx.x * blockDim.x + threadIdx.x;   // over B*S*H/4
    if (i >= Bb * Ss * Hh / 4) return;
    int base = i << 2;
    int row = base >> 10;          // b*S + s
    int col = base & 1023;
    int h = col >> 6, d = col & 63;
    int b = row >> 11, s = row & 2047;
    size_t orow = ((size_t)(b * NHh + h) * Ss + s) * 192;

    float4 q = *(const float4*)(qa + (size_t)row * Hh + col);
    float4 k = *(const float4*)(ka + (size_t)row * Hh + col);

    __nv_bfloat16 qh0 = __float2bfloat16(q.x), qh1 = __float2bfloat16(q.y);
    __nv_bfloat16 qh2 = __float2bfloat16(q.z), qh3 = __float2bfloat16(q.w);
    __nv_bfloat162 qh01(qh0, qh1), qh23(qh2, qh3);
    __nv_bfloat162 ql01(__float2bfloat16(q.x - __bfloat162float(qh0)),
                        __float2bfloat16(q.y - __bfloat162float(qh1)));
    __nv_bfloat162 ql23(__float2bfloat16(q.z - __bfloat162float(qh2)),
                        __float2bfloat16(q.w - __bfloat162float(qh3)));
    // Q: [hi | lo | hi]
    ((__nv_bfloat162*)(Q2 + orow + d))[0] = qh01;       ((__nv_bfloat162*)(Q2 + orow + d))[1] = qh23;
    ((__nv_bfloat162*)(Q2 + orow + 64 + d))[0] = ql01;  ((__nv_bfloat162*)(Q2 + orow + 64 + d))[1] = ql23;
    ((__nv_bfloat162*)(Q2 + orow + 128 + d))[0] = qh01; ((__nv_bfloat162*)(Q2 + orow + 128 + d))[1] = qh23;

    __nv_bfloat16 kh0 = __float2bfloat16(k.x), kh1 = __float2bfloat16(k.y);
    __nv_bfloat16 kh2 = __float2bfloat16(k.z), kh3 = __float2bfloat16(k.w);
    __nv_bfloat162 kh01(kh0, kh1), kh23(kh2, kh3);
    __nv_bfloat162 kl01(__float2bfloat16(k.x - __bfloat162float(kh0)),
                        __float2bfloat16(k.y - __bfloat162float(kh1)));
    __nv_bfloat162 kl23(__float2bfloat16(k.z - __bfloat162float(kh2)),
                        __float2bfloat16(k.w - __bfloat162float(kh3)));
    // K: [hi | hi | lo]
    ((__nv_bfloat162*)(K2 + orow + d))[0] = kh01;       ((__nv_bfloat162*)(K2 + orow + d))[1] = kh23;
    ((__nv_bfloat162*)(K2 + orow + 64 + d))[0] = kh01;  ((__nv_bfloat162*)(K2 + orow + 64 + d))[1] = kh23;
    ((__nv_bfloat162*)(K2 + orow + 128 + d))[0] = kl01; ((__nv_bfloat162*)(K2 + orow + 128 + d))[1] = kl23;
}

// ====== A -> transposed V hi/lo: [bh*64+d, s] ===============================
__global__ void __launch_bounds__(256) v_split(
    const float* __restrict__ A,
    __nv_bfloat16* __restrict__ Vth, __nv_bfloat16* __restrict__ Vtl)
{
    __shared__ float tile[64][65];
    int bh = blockIdx.x;           // b*NH + h
    int st = blockIdx.y;           // seq tile of 64
    int b = bh >> 4, h = bh & 15;
    int tid = threadIdx.x;

    int r = tid >> 2;
    int c0 = (tid & 3) * 16;
    const float* src = A + ((size_t)(b * Ss + st * 64 + r)) * Hh + h * 64 + c0;
#pragma unroll
    for (int t = 0; t < 4; t++) {
        float4 v = *(const float4*)(src + t * 4);
        tile[r][c0 + t * 4 + 0] = v.x; tile[r][c0 + t * 4 + 1] = v.y;
        tile[r][c0 + t * 4 + 2] = v.z; tile[r][c0 + t * 4 + 3] = v.w;
    }
    __syncthreads();

    int d = tid >> 2;
    int k0 = (tid & 3) * 16;
    uint32_t wh[8], wl[8];
#pragma unroll
    for (int t = 0; t < 8; t++) {
        float v0 = tile[k0 + 2 * t][d], v1 = tile[k0 + 2 * t + 1][d];
        __nv_bfloat16 h0 = __float2bfloat16(v0), h1 = __float2bfloat16(v1);
        __nv_bfloat162 hp(h0, h1);
        __nv_bfloat162 lp(__float2bfloat16(v0 - __bfloat162float(h0)),
                          __float2bfloat16(v1 - __bfloat162float(h1)));
        wh[t] = *(uint32_t*)&hp; wl[t] = *(uint32_t*)&lp;
    }
    size_t off = ((size_t)bh * 64 + d) * Ss + st * 64 + k0;
    *(uint4*)(Vth + off)     = make_uint4(wh[0], wh[1], wh[2], wh[3]);
    *(uint4*)(Vth + off + 8) = make_uint4(wh[4], wh[5], wh[6], wh[7]);
    *(uint4*)(Vtl + off)     = make_uint4(wl[0], wl[1], wl[2], wl[3]);
    *(uint4*)(Vtl + off + 8) = make_uint4(wl[4], wl[5], wl[6], wl[7]);
}

// ---------------- HMMA flash attention (64 q-rows/CTA, 4 warps) -------------
// smem layout (bf16 elems): Qs[64][200] | Ks[64][200] | Vh[64][72] | Vl[64][72]
#define FQ(r, c)  fsm[(r) * 200 + (c)]
#define FK(r, c)  fsm[12800 + (r) * 200 + (c)]
#define FVH(r, c) fsm[25600 + (r) * 72 + (c)]
#define FVL(r, c) fsm[30208 + (r) * 72 + (c)]
#define FLASH_SMEM (34816 * 2)

__global__ void __launch_bounds__(128, 3) flash_hmma(
    const __nv_bfloat16* __restrict__ Q2, const __nv_bfloat16* __restrict__ K2,
    const __nv_bfloat16* __restrict__ Vth, const __nv_bfloat16* __restrict__ Vtl,
    float* __restrict__ Outh)
{
    extern __shared__ __nv_bfloat16 fsm[];
    const int qt = (int)gridDim.x - 1 - (int)blockIdx.x;   // long first
    const int h  = blockIdx.y;
    const int b  = blockIdx.z;
    const int tid = threadIdx.x;
    const int w = tid >> 5;
    const int lane = tid & 31;
    const int wrow = w * 16;

    const size_t bhS  = ((size_t)(b * NHh + h)) * Ss;
    const size_t bh64 = ((size_t)(b * NHh + h)) * 64;
    const __nv_bfloat16* Qsrc = Q2 + (bhS + qt * 64) * 192;

    // load Q tile (group committed; first in-loop wait covers it)
    for (int i = tid; i < 1536; i += 128) {
        int r = i / 24, c = (i % 24) * 8;
        cp_async16(&FQ(r, c), Qsrc + (size_t)r * 192 + c);
    }
    CP_COMMIT();

    float acc[8][4];
#pragma unroll
    for (int j = 0; j < 8; j++)
#pragma unroll
        for (int q = 0; q < 4; q++) acc[j][q] = 0.f;
    float m0 = -1e30f, m1 = -1e30f, l0 = 0.f, l1 = 0.f;

    for (int kt = 0; kt <= qt; kt++) {
        // load K + V tiles
        const __nv_bfloat16* Ksrc = K2 + (bhS + kt * 64) * 192;
        for (int i = tid; i < 1536; i += 128) {
            int r = i / 24, c = (i % 24) * 8;
            cp_async16(&FK(r, c), Ksrc + (size_t)r * 192 + c);
        }
        const __nv_bfloat16* Vhsrc = Vth + bh64 * Ss + kt * 64;
        const __nv_bfloat16* Vlsrc = Vtl + bh64 * Ss + kt * 64;
        for (int i = tid; i < 512; i += 128) {
            int d = i >> 3, c = (i & 7) * 8;
            cp_async16(&FVH(d, c), Vhsrc + (size_t)d * Ss + c);
            cp_async16(&FVL(d, c), Vlsrc + (size_t)d * Ss + c);
        }
        CP_COMMIT();
        CP_WAIT0();
        __syncthreads();

        // ---- S = Q @ K^T over 192 split dims ----
        float sv[8][4];
#pragma unroll
        for (int j = 0; j < 8; j++)
#pragma unroll
            for (int q = 0; q < 4; q++) sv[j][q] = 0.f;

#pragma unroll
        for (int ks = 0; ks < 12; ks++) {
            uint32_t a[4];
            ldmat_x4(a, smem_u32(&FQ(wrow + (lane & 15), ks * 16 + (lane >> 4) * 8)));
#pragma unroll
            for (int g = 0; g < 4; g++) {
                uint32_t bfr[4];
                ldmat_x4(bfr, smem_u32(&FK(g * 16 + (lane & 7) + ((lane >> 4) & 1) * 8,
                                           ks * 16 + ((lane >> 3) & 1) * 8)));
                { uint32_t bb[2] = {bfr[0], bfr[1]}; mma_bf16(sv[2 * g], a, bb); }
                { uint32_t bb[2] = {bfr[2], bfr[3]}; mma_bf16(sv[2 * g + 1], a, bb); }
            }
        }

        // scale
#pragma unroll
        for (int j = 0; j < 8; j++)
#pragma unroll
            for (int q = 0; q < 4; q++) sv[j][q] *= SCALE;

        // causal mask (only diagonal tile)
        if (kt == qt) {
            int rb0 = wrow + (lane >> 2);
            int cb  = (lane & 3) * 2;
#pragma unroll
            for (int j = 0; j < 8; j++) {
                int c0 = j * 8 + cb;
                if (c0     > rb0)     sv[j][0] = -1e30f;
                if (c0 + 1 > rb0)     sv[j][1] = -1e30f;
                if (c0     > rb0 + 8) sv[j][2] = -1e30f;
                if (c0 + 1 > rb0 + 8) sv[j][3] = -1e30f;
            }
        }

        // ---- online softmax ----
        float rm0 = -1e30f, rm1 = -1e30f;
#pragma unroll
        for (int j = 0; j < 8; j++) {
            rm0 = fmaxf(rm0, fmaxf(sv[j][0], sv[j][1]));
            rm1 = fmaxf(rm1, fmaxf(sv[j][2], sv[j][3]));
        }
        rm0 = fmaxf(rm0, __shfl_xor_sync(0xffffffffu, rm0, 1));
        rm0 = fmaxf(rm0, __shfl_xor_sync(0xffffffffu, rm0, 2));
        rm1 = fmaxf(rm1, __shfl_xor_sync(0xffffffffu, rm1, 1));
        rm1 = fmaxf(rm1, __shfl_xor_sync(0xffffffffu, rm1, 2));
        float mn0 = fmaxf(m0, rm0), mn1 = fmaxf(m1, rm1);
        float c0 = __expf(m0 - mn0), c1 = __expf(m1 - mn1);
        float rs0 = 0.f, rs1 = 0.f;
#pragma unroll
        for (int j = 0; j < 8; j++) {
            sv[j][0] = __expf(sv[j][0] - mn0); rs0 += sv[j][0];
            sv[j][1] = __expf(sv[j][1] - mn0); rs0 += sv[j][1];
            sv[j][2] = __expf(sv[j][2] - mn1); rs1 += sv[j][2];
            sv[j][3] = __expf(sv[j][3] - mn1); rs1 += sv[j][3];
        }
        rs0 += __shfl_xor_sync(0xffffffffu, rs0, 1);
        rs0 += __shfl_xor_sync(0xffffffffu, rs0, 2);
        rs1 += __shfl_xor_sync(0xffffffffu, rs1, 1);
        rs1 += __shfl_xor_sync(0xffffffffu, rs1, 2);
        l0 = l0 * c0 + rs0; l1 = l1 * c1 + rs1;
#pragma unroll
        for (int j = 0; j < 8; j++) {
            acc[j][0] *= c0; acc[j][1] *= c0;
            acc[j][2] *= c1; acc[j][3] *= c1;
        }
        m0 = mn0; m1 = mn1;

        // ---- pack P into hi/lo A-fragments ----
        uint32_t phi[4][4], plo[4][4];
#pragma unroll
        for (int kb = 0; kb < 4; kb++) {
            int j0 = 2 * kb, j1 = 2 * kb + 1;
            float r00 = sv[j0][0] - __bfloat162float(__float2bfloat16(sv[j0][0]));
            float r01 = sv[j0][1] - __bfloat162float(__float2bfloat16(sv[j0][1]));
            float r02 = sv[j0][2] - __bfloat162float(__float2bfloat16(sv[j0][2]));
            float r03 = sv[j0][3] - __bfloat162float(__float2bfloat16(sv[j0][3]));
            float r10 = sv[j1][0] - __bfloat162float(__float2bfloat16(sv[j1][0]));
            float r11 = sv[j1][1] - __bfloat162float(__float2bfloat16(sv[j1][1]));
            float r12 = sv[j1][2] - __bfloat162float(__float2bfloat16(sv[j1][2]));
            float r13 = sv[j1][3] - __bfloat162float(__float2bfloat16(sv[j1][3]));
            phi[kb][0] = pack_bf2(sv[j0][0], sv[j0][1]);
            phi[kb][1] = pack_bf2(sv[j0][2], sv[j0][3]);
            phi[kb][2] = pack_bf2(sv[j1][0], sv[j1][1]);
            phi[kb][3] = pack_bf2(sv[j1][2], sv[j1][3]);
            plo[kb][0] = pack_bf2(r00, r01);
            plo[kb][1] = pack_bf2(r02, r03);
            plo[kb][2] = pack_bf2(r10, r11);
            plo[kb][3] = pack_bf2(r12, r13);
        }

        // ---- acc += P_hi@V_hi + P_lo@V_hi + P_hi@V_lo ----
#pragma unroll
        for (int g = 0; g < 4; g++) {
#pragma unroll
            for (int kb = 0; kb < 4; kb++) {
                uint32_t vh[4], vl[4];
                uint32_t rowa = g * 16 + (lane & 7) + ((lane >> 4) & 1) * 8;
                uint32_t cola = kb * 16 + ((lane >> 3) & 1) * 8;
                ldmat_x4(vh, smem_u32(&FVH(rowa, cola)));
                ldmat_x4(vl, smem_u32(&FVL(rowa, cola)));
                { uint32_t bb[2] = {vh[0], vh[1]};
                  mma_bf16(acc[2 * g], phi[kb], bb);
                  mma_bf16(acc[2 * g], plo[kb], bb); }
                { uint32_t bb[2] = {vh[2], vh[3]};
                  mma_bf16(acc[2 * g + 1], phi[kb], bb);
                  mma_bf16(acc[2 * g + 1], plo[kb], bb); }
                { uint32_t bb[2] = {vl[0], vl[1]};
                  mma_bf16(acc[2 * g], phi[kb], bb); }
                { uint32_t bb[2] = {vl[2], vl[3]};
                  mma_bf16(acc[2 * g + 1], phi[kb], bb); }
            }
        }
        __syncthreads();   // done reading K/V smem before next tile's loads
    }

    // ---- write out ----
    float i0 = 1.f / l0, i1 = 1.f / l1;
    int r0 = qt * 64 + wrow + (lane >> 2);
    size_t ro = ((size_t)b * Ss + r0) * Hh + h * 64;
#pragma unroll
    for (int j = 0; j < 8; j++) {
        int cc = j * 8 + (lane & 3) * 2;
        float2 v0 = {acc[j][0] * i0, acc[j][1] * i0};
        float2 v1 = {acc[j][2] * i1, acc[j][3] * i1};
        *(float2*)(Outh + ro + cc)          = v0;
        *(float2*)(Outh + ro + 8 * Hh + cc) = v1;
    }
}

// ---------------- launch -----------------------------------------------------
extern "C" void kernel_launch(void* const* d_in, const int* in_sizes, int n_in,
                              void* d_out, int out_size)
{
    const float* hs   = (const float*)d_in[0];
    const float* Wqkv = (const float*)d_in[1];
    const float* bqkv = (const float*)d_in[2];
    const float* Wqa  = (const float*)d_in[3];
    const float* bqa  = (const float*)d_in[4];
    const float* Wka  = (const float*)d_in[5];
    const float* bka  = (const float*)d_in[6];
    const float* Wd   = (const float*)d_in[7];
    const float* bd   = (const float*)d_in[8];
    float* out = (float*)d_out;

    float *qkv, *A, *qa, *ka, *oh;
    __nv_bfloat16 *hs2, *A2, *oh2, *Wqkv2, *Wqa2, *Wka2, *Wd2;
    __nv_bfloat16 *Q2, *K2, *Vth, *Vtl;
    cudaGetSymbolAddress((void**)&qkv, g_qkv);
    cudaGetSymbolAddress((void**)&A,   g_A);
    cudaGetSymbolAddress((void**)&qa,  g_qa);
    cudaGetSymbolAddress((void**)&ka,  g_ka);
    cudaGetSymbolAddress((void**)&oh,  g_oh);
    cudaGetSymbolAddress((void**)&hs2,   g_hs2);
    cudaGetSymbolAddress((void**)&A2,    g_A2);
    cudaGetSymbolAddress((void**)&oh2,   g_oh2);
    cudaGetSymbolAddress((void**)&Wqkv2, g_Wqkv2);
    cudaGetSymbolAddress((void**)&Wqa2,  g_Wqa2);
    cudaGetSymbolAddress((void**)&Wka2,  g_Wka2);
    cudaGetSymbolAddress((void**)&Wd2,   g_Wd2);
    cudaGetSymbolAddress((void**)&Q2,  g_Q2);
    cudaGetSymbolAddress((void**)&K2,  g_K2);
    cudaGetSymbolAddress((void**)&Vth, g_Vth);
    cudaGetSymbolAddress((void**)&Vtl, g_Vtl);

    cudaFuncSetAttribute(flash_hmma, cudaFuncAttributeMaxDynamicSharedMemorySize,
                         FLASH_SMEM);

    const int M = Bb * Ss;          // 4096

    auto conv = [](const float* x, __nv_bfloat16* y, int elems, int mode) {
        int n4 = elems / 4;
        split_bf16<<<(n4 + 255) / 256, 256>>>(x, y, n4, mode);
    };

    conv(hs,   hs2,   M * Hh,      0);
    conv(Wqkv, Wqkv2, 3 * Hh * Hh, 1);
    conv(Wqa,  Wqa2,  Hh * Hh,     1);
    conv(Wka,  Wka2,  Hh * Hh,     1);
    conv(Wd,   Wd2,   Hh * Hh,     1);

    // 1) qkv = hs @ Wqkv^T + bqkv
    hmma_gemm<<<dim3(3 * Hh / 128, M / 128), 256>>>(hs2, Wqkv2, bqkv, qkv, M, 3 * Hh);

    // 2) RoPE in-place on q,k
    {
        int total = Bb * Ss * NHh * 2 * (RDd / 2);
        rope_kernel<<<(total + 255) / 256, 256>>>(qkv);
    }

    // 3) sliding-window attention -> A
    window_attn<<<(Bb * NHh * Ss) * 32 / 256, 256>>>(qkv, A);

    // 4) qa = A @ Wqa^T + bqa ; ka = A @ Wka^T + bka
    conv(A, A2, M * Hh, 0);
    hmma_gemm<<<dim3(Hh / 128, M / 128), 256>>>(A2, Wqa2, bqa, qa, M, Hh);
    hmma_gemm<<<dim3(Hh / 128, M / 128), 256>>>(A2, Wka2, bka, ka, M, Hh);

    // 5) full causal attention (HMMA) -> oh
    qk_split<<<(Bb * Ss * Hh / 4 + 255) / 256, 256>>>(qa, ka, Q2, K2);
    v_split<<<dim3(Bb * NHh, Ss / 64), 256>>>(A, Vth, Vtl);
    flash_hmma<<<dim3(Ss / 64, NHh, Bb), 128, FLASH_SMEM>>>(Q2, K2, Vth, Vtl, oh);

    // 6) out = oh @ Wd^T + bd
    conv(oh, oh2, M * Hh, 0);
    hmma_gemm<<<dim3(Hh / 128, M / 128), 256>>>(oh2, Wd2, bd, out, M, Hh);
}

// round 8
// speedup vs baseline: 2.3332x; 1.0169x over previous
#include <cuda_runtime.h>
#include <cuda_bf16.h>
#include <math.h>
#include <stdint.h>

#define Bb   2
#define Ss   2048
#define Hh   1024
#define NHh  16
#define HDd  64
#define RDd  16
#define Ww   16
#define SCALE 0.125f

// GEMM split width: [hi | lo | hi] x [hi | hi | lo] along K
#define KP   3072
#define NIT  (KP / 32)

// ---------------- scratch (device globals: no allocations allowed) ----------
__device__ float g_qkv[(size_t)Bb * Ss * 3 * Hh];   // [B*S, 3H]
__device__ float g_A  [(size_t)Bb * Ss * Hh];       // window-attn out (fp32, for v_split)

// bf16 3-segment split operands, layout [rows, 3072]
__device__ __nv_bfloat16 g_hs2  [(size_t)Bb * Ss * KP];
__device__ __nv_bfloat16 g_A2   [(size_t)Bb * Ss * KP];
__device__ __nv_bfloat16 g_oh2  [(size_t)Bb * Ss * KP];
__device__ __nv_bfloat16 g_Wqkv2[(size_t)3 * Hh * KP];
__device__ __nv_bfloat16 g_Wqka2[(size_t)2 * Hh * KP];   // [Wqa ; Wka] stacked
__device__ __nv_bfloat16 g_Wd2  [(size_t)Hh * KP];

// flash attention operands
__device__ __nv_bfloat16 g_Q2 [(size_t)Bb * NHh * Ss * 192];  // [bh, s, 192] hi|lo|hi
__device__ __nv_bfloat16 g_K2 [(size_t)Bb * NHh * Ss * 192];  // [bh, s, 192] hi|hi|lo
__device__ __nv_bfloat16 g_Vth[(size_t)Bb * NHh * HDd * Ss];  // [bh*64+d, s] hi
__device__ __nv_bfloat16 g_Vtl[(size_t)Bb * NHh * HDd * Ss];  // [bh*64+d, s] lo

// =================== helpers ================================================
__device__ __forceinline__ uint32_t smem_u32(const void* p) {
    uint32_t a;
    asm("{ .reg .u64 t; cvta.to.shared.u64 t, %1; cvt.u32.u64 %0, t; }" : "=r"(a) : "l"(p));
    return a;
}
__device__ __forceinline__ void cp_async16(void* s, const void* g) {
    uint32_t sa = smem_u32(s);
    asm volatile("cp.async.ca.shared.global [%0], [%1], 16;" :: "r"(sa), "l"(g));
}
#define CP_COMMIT() asm volatile("cp.async.commit_group;" ::: "memory")
#define CP_WAIT1()  asm volatile("cp.async.wait_group 1;" ::: "memory")
#define CP_WAIT0()  asm volatile("cp.async.wait_group 0;" ::: "memory")

__device__ __forceinline__ void ldmat_x4(uint32_t* r, uint32_t addr) {
    asm volatile("ldmatrix.sync.aligned.m8n8.x4.shared.b16 {%0,%1,%2,%3}, [%4];"
        : "=r"(r[0]), "=r"(r[1]), "=r"(r[2]), "=r"(r[3]) : "r"(addr));
}
__device__ __forceinline__ void mma_bf16(float* d, const uint32_t* a, const uint32_t* b) {
    asm volatile(
        "mma.sync.aligned.m16n8k16.row.col.f32.bf16.bf16.f32 "
        "{%0,%1,%2,%3}, {%4,%5,%6,%7}, {%8,%9}, {%0,%1,%2,%3};"
        : "+f"(d[0]), "+f"(d[1]), "+f"(d[2]), "+f"(d[3])
        : "r"(a[0]), "r"(a[1]), "r"(a[2]), "r"(a[3]), "r"(b[0]), "r"(b[1]));
}
__device__ __forceinline__ uint32_t pack_bf2(float x, float y) {
    __nv_bfloat162 t(__float2bfloat16(x), __float2bfloat16(y));
    return *(uint32_t*)&t;
}

// ====== fp32 -> bf16 3-segment split (GEMM operands) ========================
__global__ void split_bf16(const float* __restrict__ X, __nv_bfloat16* __restrict__ Y,
                           int n4, int mode)
{
    int i = blockIdx.x * blockDim.x + threadIdx.x;
    if (i >= n4) return;
    int base = i << 2;
    float4 v = *(const float4*)(X + base);
    int r = base >> 10;
    int c = base & 1023;
    __nv_bfloat16 h0 = __float2bfloat16(v.x), h1 = __float2bfloat16(v.y);
    __nv_bfloat16 h2 = __float2bfloat16(v.z), h3 = __float2bfloat16(v.w);
    __nv_bfloat16 l0 = __float2bfloat16(v.x - __bfloat162float(h0));
    __nv_bfloat16 l1 = __float2bfloat16(v.y - __bfloat162float(h1));
    __nv_bfloat16 l2 = __float2bfloat16(v.z - __bfloat162float(h2));
    __nv_bfloat16 l3 = __float2bfloat16(v.w - __bfloat162float(h3));
    __nv_bfloat16* row = Y + (size_t)r * KP + c;
    __nv_bfloat162 hA(h0, h1), hB(h2, h3), lA(l0, l1), lB(l2, l3);
    ((__nv_bfloat162*)(row))[0] = hA; ((__nv_bfloat162*)(row))[1] = hB;
    if (mode == 0) {   // A-side: [hi | lo | hi]
        ((__nv_bfloat162*)(row + 1024))[0] = lA; ((__nv_bfloat162*)(row + 1024))[1] = lB;
        ((__nv_bfloat162*)(row + 2048))[0] = hA; ((__nv_bfloat162*)(row + 2048))[1] = hB;
    } else {           // B-side: [hi | hi | lo]
        ((__nv_bfloat162*)(row + 1024))[0] = hA; ((__nv_bfloat162*)(row + 1024))[1] = hB;
        ((__nv_bfloat162*)(row + 2048))[0] = lA; ((__nv_bfloat162*)(row + 2048))[1] = lB;
    }
}

// ======== HMMA GEMM:  C[M,N] = A2[M,3072] @ B2[N,3072]^T + bias[N] ==========
__global__ void __launch_bounds__(256) hmma_gemm(
    const __nv_bfloat16* __restrict__ A2, const __nv_bfloat16* __restrict__ B2,
    const float* __restrict__ bias, float* __restrict__ C, int M, int N)
{
    __shared__ __align__(16) __nv_bfloat16 sm[2][2][128][40];

    const int tid = threadIdx.x;
    const int wid = tid >> 5;
    const int lane = tid & 31;
    const int bm = blockIdx.y * 128;
    const int bn = blockIdx.x * 128;
    const int wm = wid & 1;
    const int wn = wid >> 1;

    float acc[4][4][4];
#pragma unroll
    for (int mi = 0; mi < 4; mi++)
#pragma unroll
        for (int ni = 0; ni < 4; ni++)
#pragma unroll
            for (int q = 0; q < 4; q++) acc[mi][ni][q] = 0.f;

    auto load_tile = [&](int buf, int k0) {
#pragma unroll
        for (int i = 0; i < 2; i++) {
            int c = tid + i * 256;
            int r = c >> 2;
            int kk = (c & 3) * 8;
            cp_async16(&sm[buf][0][r][kk], A2 + (size_t)(bm + r) * KP + k0 + kk);
            cp_async16(&sm[buf][1][r][kk], B2 + (size_t)(bn + r) * KP + k0 + kk);
        }
        CP_COMMIT();
    };

    load_tile(0, 0);

    for (int it = 0; it < NIT; it++) {
        const int buf = it & 1;
        if (it + 1 < NIT) {
            load_tile(buf ^ 1, (it + 1) * 32);
            CP_WAIT1();
        } else {
            CP_WAIT0();
        }
        __syncthreads();

#pragma unroll
        for (int ks = 0; ks < 2; ks++) {
            uint32_t af[4][4];
#pragma unroll
            for (int mi = 0; mi < 4; mi++) {
                uint32_t addr = smem_u32(
                    &sm[buf][0][wm * 64 + mi * 16 + (lane & 15)][ks * 16 + (lane >> 4) * 8]);
                ldmat_x4(af[mi], addr);
            }
            uint32_t bf[2][4];
#pragma unroll
            for (int g = 0; g < 2; g++) {
                uint32_t addr = smem_u32(
                    &sm[buf][1][wn * 32 + g * 16 + (lane & 7) + ((lane >> 4) & 1) * 8]
                               [ks * 16 + ((lane >> 3) & 1) * 8]);
                ldmat_x4(bf[g], addr);
            }
#pragma unroll
            for (int mi = 0; mi < 4; mi++)
#pragma unroll
                for (int ni = 0; ni < 4; ni++) {
                    uint32_t bb[2] = {bf[ni >> 1][(ni & 1) * 2],
                                      bf[ni >> 1][(ni & 1) * 2 + 1]};
                    mma_bf16(acc[mi][ni], af[mi], bb);
                }
        }
        __syncthreads();
    }

#pragma unroll
    for (int mi = 0; mi < 4; mi++) {
        int row0 = bm + wm * 64 + mi * 16 + (lane >> 2);
#pragma unroll
        for (int ni = 0; ni < 4; ni++) {
            int col = bn + wn * 32 + ni * 8 + (lane & 3) * 2;
            float b0 = bias[col], b1 = bias[col + 1];
            float2 v0 = {acc[mi][ni][0] + b0, acc[mi][ni][1] + b1};
            float2 v1 = {acc[mi][ni][2] + b0, acc[mi][ni][3] + b1};
            *(float2*)(C + (size_t)row0 * N + col)       = v0;
            *(float2*)(C + (size_t)(row0 + 8) * N + col) = v1;
        }
    }
}

// ======== fused qa/ka GEMM: A2 @ [Wqa;Wka]^T, epilogue -> Q2/K2 split =======
__global__ void __launch_bounds__(256) hmma_gemm_qk(
    const __nv_bfloat16* __restrict__ A2, const __nv_bfloat16* __restrict__ B2,
    const float* __restrict__ bqa, const float* __restrict__ bka,
    __nv_bfloat16* __restrict__ Q2, __nv_bfloat16* __restrict__ K2)
{
    __shared__ __align__(16) __nv_bfloat16 sm[2][2][128][40];

    const int tid = threadIdx.x;
    const int wid = tid >> 5;
    const int lane = tid & 31;
    const int bm = blockIdx.y * 128;
    const int bn = blockIdx.x * 128;      // over 2048 (qa: 0..1023, ka: 1024..2047)
    const int wm = wid & 1;
    const int wn = wid >> 1;

    float acc[4][4][4];
#pragma unroll
    for (int mi = 0; mi < 4; mi++)
#pragma unroll
        for (int ni = 0; ni < 4; ni++)
#pragma unroll
            for (int q = 0; q < 4; q++) acc[mi][ni][q] = 0.f;

    auto load_tile = [&](int buf, int k0) {
#pragma unroll
        for (int i = 0; i < 2; i++) {
            int c = tid + i * 256;
            int r = c >> 2;
            int kk = (c & 3) * 8;
            cp_async16(&sm[buf][0][r][kk], A2 + (size_t)(bm + r) * KP + k0 + kk);
            cp_async16(&sm[buf][1][r][kk], B2 + (size_t)(bn + r) * KP + k0 + kk);
        }
        CP_COMMIT();
    };

    load_tile(0, 0);

    for (int it = 0; it < NIT; it++) {
        const int buf = it & 1;
        if (it + 1 < NIT) {
            load_tile(buf ^ 1, (it + 1) * 32);
            CP_WAIT1();
        } else {
            CP_WAIT0();
        }
        __syncthreads();

#pragma unroll
        for (int ks = 0; ks < 2; ks++) {
            uint32_t af[4][4];
#pragma unroll
            for (int mi = 0; mi < 4; mi++) {
                uint32_t addr = smem_u32(
                    &sm[buf][0][wm * 64 + mi * 16 + (lane & 15)][ks * 16 + (lane >> 4) * 8]);
                ldmat_x4(af[mi], addr);
            }
            uint32_t bf[2][4];
#pragma unroll
            for (int g = 0; g < 2; g++) {
                uint32_t addr = smem_u32(
                    &sm[buf][1][wn * 32 + g * 16 + (lane & 7) + ((lane >> 4) & 1) * 8]
                               [ks * 16 + ((lane >> 3) & 1) * 8]);
                ldmat_x4(bf[g], addr);
            }
#pragma unroll
            for (int mi = 0; mi < 4; mi++)
#pragma unroll
                for (int ni = 0; ni < 4; ni++) {
                    uint32_t bb[2] = {bf[ni >> 1][(ni & 1) * 2],
                                      bf[ni >> 1][(ni & 1) * 2 + 1]};
                    mma_bf16(acc[mi][ni], af[mi], bb);
                }
        }
        __syncthreads();
    }

    // epilogue: split to bf16 hi/lo, write Q2 ([hi|lo|hi]) or K2 ([hi|hi|lo])
    const bool isK = (bn >= 1024);
    const float* bias = isK ? bka : bqa;
    __nv_bfloat16* dst = isK ? K2 : Q2;
    const int cb = isK ? bn - 1024 : bn;

#pragma unroll
    for (int mi = 0; mi < 4; mi++) {
        int row0 = bm + wm * 64 + mi * 16 + (lane >> 2);
        int b = row0 >> 11, s = row0 & 2047;
#pragma unroll
        for (int ni = 0; ni < 4; ni++) {
            int col = cb + wn * 32 + ni * 8 + (lane & 3) * 2;
            int hh = col >> 6, d = col & 63;
            size_t or0 = ((size_t)(b * NHh + hh) * Ss + s) * 192 + d;
            float b0 = bias[col], b1 = bias[col + 1];
#pragma unroll
            for (int half = 0; half < 2; half++) {
                float v0 = acc[mi][ni][2 * half + 0] + b0;
                float v1 = acc[mi][ni][2 * half + 1] + b1;
                __nv_bfloat16 h0 = __float2bfloat16(v0), h1 = __float2bfloat16(v1);
                uint32_t hp = pack_bf2(v0, v1);
                uint32_t lp = pack_bf2(v0 - __bfloat162float(h0),
                                       v1 - __bfloat162float(h1));
                size_t o = or0 + (size_t)half * 8 * 192;
                if (!isK) {   // Q: [hi | lo | hi]
                    *(uint32_t*)(dst + o)       = hp;
                    *(uint32_t*)(dst + o + 64)  = lp;
                    *(uint32_t*)(dst + o + 128) = hp;
                } else {      // K: [hi | hi | lo]
                    *(uint32_t*)(dst + o)       = hp;
                    *(uint32_t*)(dst + o + 64)  = hp;
                    *(uint32_t*)(dst + o + 128) = lp;
                }
            }
        }
    }
}

// ---------------- RoPE on q,k first RD dims (in-place in qkv) ---------------
__global__ void rope_kernel(float* __restrict__ qkv)
{
    int idx = blockIdx.x * blockDim.x + threadIdx.x;
    if (idx >= Bb * Ss * NHh * 2 * (RDd / 2)) return;
    int i  = idx & 7;
    int qk = (idx >> 3) & 1;
    int h  = (idx >> 4) & 15;
    int bs = idx >> 8;
    int s  = bs & (Ss - 1);

    float* p = qkv + (size_t)bs * (3 * Hh) + qk * Hh + h * HDd;
    float inv_freq = powf(10000.f, -(float)(2 * i) / (float)RDd);
    float ang = (float)s * inv_freq;
    float sn, cs;
    sincosf(ang, &sn, &cs);
    float x1 = p[i], x2 = p[i + 8];
    p[i]     = x1 * cs - x2 * sn;
    p[i + 8] = x2 * cs + x1 * sn;
}

// ------ sliding-window attention; writes A (fp32) and A2 (3-seg split) -----
__global__ void __launch_bounds__(256) window_attn(
    const float* __restrict__ qkv, float* __restrict__ A,
    __nv_bfloat16* __restrict__ A2)
{
    int gw   = (blockIdx.x * blockDim.x + threadIdx.x) >> 5;
    int lane = threadIdx.x & 31;
    int s = gw & (Ss - 1);
    int h = (gw >> 11) & (NHh - 1);
    int b = gw >> 15;

    const float* qr = qkv + (size_t)(b * Ss + s) * (3 * Hh) + h * HDd;
    float q0 = qr[lane], q1 = qr[lane + 32];

    float sc[Ww];
#pragma unroll
    for (int w = 0; w < Ww; w++) {
        int idx = s - (Ww - 1) + w;
        float p = 0.f;
        if (idx >= 0) {
            const float* kr = qkv + (size_t)(b * Ss + idx) * (3 * Hh) + Hh + h * HDd;
            p = q0 * kr[lane] + q1 * kr[lane + 32];
        }
#pragma unroll
        for (int off = 16; off; off >>= 1)
            p += __shfl_xor_sync(0xffffffffu, p, off);
        sc[w] = (idx >= 0) ? p * SCALE : -1e30f;
    }

    float mx = sc[0];
#pragma unroll
    for (int w = 1; w < Ww; w++) mx = fmaxf(mx, sc[w]);
    float lsum = 0.f;
#pragma unroll
    for (int w = 0; w < Ww; w++) { float e = __expf(sc[w] - mx); sc[w] = e; lsum += e; }
    float inv = 1.f / lsum;

    float o0 = 0.f, o1 = 0.f;
#pragma unroll
    for (int w = 0; w < Ww; w++) {
        int idx = s - (Ww - 1) + w;
        if (idx >= 0) {
            const float* vr = qkv + (size_t)(b * Ss + idx) * (3 * Hh) + 2 * Hh + h * HDd;
            o0 += sc[w] * vr[lane];
            o1 += sc[w] * vr[lane + 32];
        }
    }
    o0 *= inv; o1 *= inv;

    size_t o = (size_t)(b * Ss + s) * Hh + h * HDd;
    A[o + lane]      = o0;
    A[o + lane + 32] = o1;

    // split write into A2 [hi | lo | hi]
    size_t r2 = (size_t)(b * Ss + s) * KP + h * HDd;
    __nv_bfloat16 h0 = __float2bfloat16(o0), h1 = __float2bfloat16(o1);
    __nv_bfloat16 l0 = __float2bfloat16(o0 - __bfloat162float(h0));
    __nv_bfloat16 l1 = __float2bfloat16(o1 - __bfloat162float(h1));
    A2[r2 + lane]             = h0; A2[r2 + lane + 32]        = h1;
    A2[r2 + 1024 + lane]      = l0; A2[r2 + 1024 + lane + 32] = l1;
    A2[r2 + 2048 + lane]      = h0; A2[r2 + 2048 + lane + 32] = h1;
}

// ====== A -> transposed V hi/lo: [bh*64+d, s] ===============================
__global__ void __launch_bounds__(256) v_split(
    const float* __restrict__ A,
    __nv_bfloat16* __restrict__ Vth, __nv_bfloat16* __restrict__ Vtl)
{
    __shared__ float tile[64][65];
    int bh = blockIdx.x;
    int st = blockIdx.y;
    int b = bh >> 4, h = bh & 15;
    int tid = threadIdx.x;

    int r = tid >> 2;
    int c0 = (tid & 3) * 16;
    const float* src = A + ((size_t)(b * Ss + st * 64 + r)) * Hh + h * 64 + c0;
#pragma unroll
    for (int t = 0; t < 4; t++) {
        float4 v = *(const float4*)(src + t * 4);
        tile[r][c0 + t * 4 + 0] = v.x; tile[r][c0 + t * 4 + 1] = v.y;
        tile[r][c0 + t * 4 + 2] = v.z; tile[r][c0 + t * 4 + 3] = v.w;
    }
    __syncthreads();

    int d = tid >> 2;
    int k0 = (tid & 3) * 16;
    uint32_t wh[8], wl[8];
#pragma unroll
    for (int t = 0; t < 8; t++) {
        float v0 = tile[k0 + 2 * t][d], v1 = tile[k0 + 2 * t + 1][d];
        __nv_bfloat16 h0 = __float2bfloat16(v0), h1 = __float2bfloat16(v1);
        __nv_bfloat162 hp(h0, h1);
        __nv_bfloat162 lp(__float2bfloat16(v0 - __bfloat162float(h0)),
                          __float2bfloat16(v1 - __bfloat162float(h1)));
        wh[t] = *(uint32_t*)&hp; wl[t] = *(uint32_t*)&lp;
    }
    size_t off = ((size_t)bh * 64 + d) * Ss + st * 64 + k0;
    *(uint4*)(Vth + off)     = make_uint4(wh[0], wh[1], wh[2], wh[3]);
    *(uint4*)(Vth + off + 8) = make_uint4(wh[4], wh[5], wh[6], wh[7]);
    *(uint4*)(Vtl + off)     = make_uint4(wl[0], wl[1], wl[2], wl[3]);
    *(uint4*)(Vtl + off + 8) = make_uint4(wl[4], wl[5], wl[6], wl[7]);
}

// -------- HMMA flash attention, double-buffered K/V, writes oh2 split -------
// smem (bf16): Q[64][200] | 2 x { K[64][200] | Vh[64][72] | Vl[64][72] }
#define FBUF 22016
#define FQ(r, c)      fsm[(r) * 200 + (c)]
#define FK(bf, r, c)  fsm[12800 + (bf) * FBUF + (r) * 200 + (c)]
#define FVH(bf, r, c) fsm[12800 + (bf) * FBUF + 12800 + (r) * 72 + (c)]
#define FVL(bf, r, c) fsm[12800 + (bf) * FBUF + 17408 + (r) * 72 + (c)]
#define FLASH_SMEM ((12800 + 2 * FBUF) * 2)

__global__ void __launch_bounds__(128, 2) flash_hmma(
    const __nv_bfloat16* __restrict__ Q2, const __nv_bfloat16* __restrict__ K2,
    const __nv_bfloat16* __restrict__ Vth, const __nv_bfloat16* __restrict__ Vtl,
    __nv_bfloat16* __restrict__ Oh2)
{
    extern __shared__ __nv_bfloat16 fsm[];
    const int qt = (int)gridDim.x - 1 - (int)blockIdx.x;   // long first
    const int h  = blockIdx.y;
    const int b  = blockIdx.z;
    const int tid = threadIdx.x;
    const int w = tid >> 5;
    const int lane = tid & 31;
    const int wrow = w * 16;

    const size_t bhS  = ((size_t)(b * NHh + h)) * Ss;
    const size_t bh64 = ((size_t)(b * NHh + h)) * 64;
    const __nv_bfloat16* Qsrc = Q2 + (bhS + qt * 64) * 192;

    auto load_kv = [&](int bf, int kt) {
        const __nv_bfloat16* Ksrc = K2 + (bhS + kt * 64) * 192;
        for (int i = tid; i < 1536; i += 128) {
            int r = i / 24, c = (i % 24) * 8;
            cp_async16(&FK(bf, r, c), Ksrc + (size_t)r * 192 + c);
        }
        const __nv_bfloat16* Vhsrc = Vth + bh64 * Ss + kt * 64;
        const __nv_bfloat16* Vlsrc = Vtl + bh64 * Ss + kt * 64;
        for (int i = tid; i < 512; i += 128) {
            int d = i >> 3, c = (i & 7) * 8;
            cp_async16(&FVH(bf, d, c), Vhsrc + (size_t)d * Ss + c);
            cp_async16(&FVL(bf, d, c), Vlsrc + (size_t)d * Ss + c);
        }
        CP_COMMIT();
    };

    // Q tile + first K/V tile
    for (int i = tid; i < 1536; i += 128) {
        int r = i / 24, c = (i % 24) * 8;
        cp_async16(&FQ(r, c), Qsrc + (size_t)r * 192 + c);
    }
    CP_COMMIT();
    load_kv(0, 0);

    float acc[8][4];
#pragma unroll
    for (int j = 0; j < 8; j++)
#pragma unroll
        for (int q = 0; q < 4; q++) acc[j][q] = 0.f;
    float m0 = -1e30f, m1 = -1e30f, l0 = 0.f, l1 = 0.f;

    for (int kt = 0; kt <= qt; kt++) {
        const int bf = kt & 1;
        __syncthreads();                 // buf bf^1 free (compute kt-1 done)
        if (kt < qt) { load_kv(bf ^ 1, kt + 1); CP_WAIT1(); }
        else         { CP_WAIT0(); }
        __syncthreads();                 // tile kt visible to all

        // ---- S = Q @ K^T over 192 split dims ----
        float sv[8][4];
#pragma unroll
        for (int j = 0; j < 8; j++)
#pragma unroll
            for (int q = 0; q < 4; q++) sv[j][q] = 0.f;

#pragma unroll
        for (int ks = 0; ks < 12; ks++) {
            uint32_t a[4];
            ldmat_x4(a, smem_u32(&FQ(wrow + (lane & 15), ks * 16 + (lane >> 4) * 8)));
#pragma unroll
            for (int g = 0; g < 4; g++) {
                uint32_t bfr[4];
                ldmat_x4(bfr, smem_u32(&FK(bf, g * 16 + (lane & 7) + ((lane >> 4) & 1) * 8,
                                           ks * 16 + ((lane >> 3) & 1) * 8)));
                { uint32_t bb[2] = {bfr[0], bfr[1]}; mma_bf16(sv[2 * g], a, bb); }
                { uint32_t bb[2] = {bfr[2], bfr[3]}; mma_bf16(sv[2 * g + 1], a, bb); }
            }
        }

#pragma unroll
        for (int j = 0; j < 8; j++)
#pragma unroll
            for (int q = 0; q < 4; q++) sv[j][q] *= SCALE;

        if (kt == qt) {
            int rb0 = wrow + (lane >> 2);
            int cb  = (lane & 3) * 2;
#pragma unroll
            for (int j = 0; j < 8; j++) {
                int c0 = j * 8 + cb;
                if (c0     > rb0)     sv[j][0] = -1e30f;
                if (c0 + 1 > rb0)     sv[j][1] = -1e30f;
                if (c0     > rb0 + 8) sv[j][2] = -1e30f;
                if (c0 + 1 > rb0 + 8) sv[j][3] = -1e30f;
            }
        }

        // ---- online softmax ----
        float rm0 = -1e30f, rm1 = -1e30f;
#pragma unroll
        for (int j = 0; j < 8; j++) {
            rm0 = fmaxf(rm0, fmaxf(sv[j][0], sv[j][1]));
            rm1 = fmaxf(rm1, fmaxf(sv[j][2], sv[j][3]));
        }
        rm0 = fmaxf(rm0, __shfl_xor_sync(0xffffffffu, rm0, 1));
        rm0 = fmaxf(rm0, __shfl_xor_sync(0xffffffffu, rm0, 2));
        rm1 = fmaxf(rm1, __shfl_xor_sync(0xffffffffu, rm1, 1));
        rm1 = fmaxf(rm1, __shfl_xor_sync(0xffffffffu, rm1, 2));
        float mn0 = fmaxf(m0, rm0), mn1 = fmaxf(m1, rm1);
        float c0 = __expf(m0 - mn0), c1 = __expf(m1 - mn1);
        float rs0 = 0.f, rs1 = 0.f;
#pragma unroll
        for (int j = 0; j < 8; j++) {
            sv[j][0] = __expf(sv[j][0] - mn0); rs0 += sv[j][0];
            sv[j][1] = __expf(sv[j][1] - mn0); rs0 += sv[j][1];
            sv[j][2] = __expf(sv[j][2] - mn1); rs1 += sv[j][2];
            sv[j][3] = __expf(sv[j][3] - mn1); rs1 += sv[j][3];
        }
        rs0 += __shfl_xor_sync(0xffffffffu, rs0, 1);
        rs0 += __shfl_xor_sync(0xffffffffu, rs0, 2);
        rs1 += __shfl_xor_sync(0xffffffffu, rs1, 1);
        rs1 += __shfl_xor_sync(0xffffffffu, rs1, 2);
        l0 = l0 * c0 + rs0; l1 = l1 * c1 + rs1;
#pragma unroll
        for (int j = 0; j < 8; j++) {
            acc[j][0] *= c0; acc[j][1] *= c0;
            acc[j][2] *= c1; acc[j][3] *= c1;
        }
        m0 = mn0; m1 = mn1;

        // ---- pack P into hi/lo A-fragments ----
        uint32_t phi[4][4], plo[4][4];
#pragma unroll
        for (int kb = 0; kb < 4; kb++) {
            int j0 = 2 * kb, j1 = 2 * kb + 1;
            float r00 = sv[j0][0] - __bfloat162float(__float2bfloat16(sv[j0][0]));
            float r01 = sv[j0][1] - __bfloat162float(__float2bfloat16(sv[j0][1]));
            float r02 = sv[j0][2] - __bfloat162float(__float2bfloat16(sv[j0][2]));
            float r03 = sv[j0][3] - __bfloat162float(__float2bfloat16(sv[j0][3]));
            float r10 = sv[j1][0] - __bfloat162float(__float2bfloat16(sv[j1][0]));
            float r11 = sv[j1][1] - __bfloat162float(__float2bfloat16(sv[j1][1]));
            float r12 = sv[j1][2] - __bfloat162float(__float2bfloat16(sv[j1][2]));
            float r13 = sv[j1][3] - __bfloat162float(__float2bfloat16(sv[j1][3]));
            phi[kb][0] = pack_bf2(sv[j0][0], sv[j0][1]);
            phi[kb][1] = pack_bf2(sv[j0][2], sv[j0][3]);
            phi[kb][2] = pack_bf2(sv[j1][0], sv[j1][1]);
            phi[kb][3] = pack_bf2(sv[j1][2], sv[j1][3]);
            plo[kb][0] = pack_bf2(r00, r01);
            plo[kb][1] = pack_bf2(r02, r03);
            plo[kb][2] = pack_bf2(r10, r11);
            plo[kb][3] = pack_bf2(r12, r13);
        }

        // ---- acc += P_hi@V_hi + P_lo@V_hi + P_hi@V_lo ----
#pragma unroll
        for (int g = 0; g < 4; g++) {
#pragma unroll
            for (int kb = 0; kb < 4; kb++) {
                uint32_t vh[4], vl[4];
                uint32_t rowa = g * 16 + (lane & 7) + ((lane >> 4) & 1) * 8;
                uint32_t cola = kb * 16 + ((lane >> 3) & 1) * 8;
                ldmat_x4(vh, smem_u32(&FVH(bf, rowa, cola)));
                ldmat_x4(vl, smem_u32(&FVL(bf, rowa, cola)));
                { uint32_t bb[2] = {vh[0], vh[1]};
                  mma_bf16(acc[2 * g], phi[kb], bb);
                  mma_bf16(acc[2 * g], plo[kb], bb); }
                { uint32_t bb[2] = {vh[2], vh[3]};
                  mma_bf16(acc[2 * g + 1], phi[kb], bb);
                  mma_bf16(acc[2 * g + 1], plo[kb], bb); }
                { uint32_t bb[2] = {vl[0], vl[1]};
                  mma_bf16(acc[2 * g], phi[kb], bb); }
                { uint32_t bb[2] = {vl[2], vl[3]};
                  mma_bf16(acc[2 * g + 1], phi[kb], bb); }
            }
        }
    }

    // ---- write out: oh2 split [hi | lo | hi] ----
    float i0 = 1.f / l0, i1 = 1.f / l1;
    int r0 = qt * 64 + wrow + (lane >> 2);
    size_t ro = ((size_t)b * Ss + r0) * KP + h * 64;
#pragma unroll
    for (int j = 0; j < 8; j++) {
        int cc = j * 8 + (lane & 3) * 2;
#pragma unroll
        for (int half = 0; half < 2; half++) {
            float v0 = acc[j][2 * half + 0] * (half ? i1 : i0);
            float v1 = acc[j][2 * half + 1] * (half ? i1 : i0);
            __nv_bfloat16 h0 = __float2bfloat16(v0), h1 = __float2bfloat16(v1);
            uint32_t hp = pack_bf2(v0, v1);
            uint32_t lp = pack_bf2(v0 - __bfloat162float(h0),
                                   v1 - __bfloat162float(h1));
            size_t o = ro + (size_t)half * 8 * KP + cc;
            *(uint32_t*)(Oh2 + o)        = hp;
            *(uint32_t*)(Oh2 + o + 1024) = lp;
            *(uint32_t*)(Oh2 + o + 2048) = hp;
        }
    }
}

// ---------------- launch -----------------------------------------------------
extern "C" void kernel_launch(void* const* d_in, const int* in_sizes, int n_in,
                              void* d_out, int out_size)
{
    const float* hs   = (const float*)d_in[0];
    const float* Wqkv = (const float*)d_in[1];
    const float* bqkv = (const float*)d_in[2];
    const float* Wqa  = (const float*)d_in[3];
    const float* bqa  = (const float*)d_in[4];
    const float* Wka  = (const float*)d_in[5];
    const float* bka  = (const float*)d_in[6];
    const float* Wd   = (const float*)d_in[7];
    const float* bd   = (const float*)d_in[8];
    float* out = (float*)d_out;

    float *qkv, *A;
    __nv_bfloat16 *hs2, *A2, *oh2, *Wqkv2, *Wqka2, *Wd2;
    __nv_bfloat16 *Q2, *K2, *Vth, *Vtl;
    cudaGetSymbolAddress((void**)&qkv, g_qkv);
    cudaGetSymbolAddress((void**)&A,   g_A);
    cudaGetSymbolAddress((void**)&hs2,   g_hs2);
    cudaGetSymbolAddress((void**)&A2,    g_A2);
    cudaGetSymbolAddress((void**)&oh2,   g_oh2);
    cudaGetSymbolAddress((void**)&Wqkv2, g_Wqkv2);
    cudaGetSymbolAddress((void**)&Wqka2, g_Wqka2);
    cudaGetSymbolAddress((void**)&Wd2,   g_Wd2);
    cudaGetSymbolAddress((void**)&Q2,  g_Q2);
    cudaGetSymbolAddress((void**)&K2,  g_K2);
    cudaGetSymbolAddress((void**)&Vth, g_Vth);
    cudaGetSymbolAddress((void**)&Vtl, g_Vtl);

    cudaFuncSetAttribute(flash_hmma, cudaFuncAttributeMaxDynamicSharedMemorySize,
                         FLASH_SMEM);

    const int M = Bb * Ss;          // 4096

    auto conv = [](const float* x, __nv_bfloat16* y, int elems, int mode) {
        int n4 = elems / 4;
        split_bf16<<<(n4 + 255) / 256, 256>>>(x, y, n4, mode);
    };

    conv(hs,   hs2,   M * Hh,      0);
    conv(Wqkv, Wqkv2, 3 * Hh * Hh, 1);
    conv(Wqa,  Wqka2,               Hh * Hh, 1);
    conv(Wka,  Wqka2 + (size_t)Hh * KP, Hh * Hh, 1);
    conv(Wd,   Wd2,   Hh * Hh,     1);

    // 1) qkv = hs @ Wqkv^T + bqkv
    hmma_gemm<<<dim3(3 * Hh / 128, M / 128), 256>>>(hs2, Wqkv2, bqkv, qkv, M, 3 * Hh);

    // 2) RoPE in-place on q,k
    {
        int total = Bb * Ss * NHh * 2 * (RDd / 2);
        rope_kernel<<<(total + 255) / 256, 256>>>(qkv);
    }

    // 3) sliding-window attention -> A (fp32) + A2 (split)
    window_attn<<<(Bb * NHh * Ss) * 32 / 256, 256>>>(qkv, A, A2);

    // 4) fused qa/ka GEMM -> Q2/K2 split layouts ; V split from A
    v_split<<<dim3(Bb * NHh, Ss / 64), 256>>>(A, Vth, Vtl);
    hmma_gemm_qk<<<dim3(2 * Hh / 128, M / 128), 256>>>(A2, Wqka2, bqa, bka, Q2, K2);

    // 5) full causal attention (HMMA, double-buffered) -> oh2 split
    flash_hmma<<<dim3(Ss / 64, NHh, Bb), 128, FLASH_SMEM>>>(Q2, K2, Vth, Vtl, oh2);

    // 6) out = oh2 @ Wd^T + bd
    hmma_gemm<<<dim3(Hh / 128, M / 128), 256>>>(oh2, Wd2, bd, out, M, Hh);
}